// round 11
// baseline (speedup 1.0000x reference)
#include <cuda_runtime.h>
#include <cuda_fp16.h>
#include <cstdint>

// Problem constants
#define B_    64
#define S_    512
#define T_    32
#define H2_   1024
#define ATT_  512
#define WSTR_ 2048

// GEMM tiling (fp16 mma.m16n8k16, fp32 accum)
#define BM 128
#define BN 128
#define BK 32
#define NIT (H2_ / BK)          // 32
#define ROWB 80                 // padded smem row bytes (conflict-free ldmatrix)
#define A_BYTES (BM * ROWB)     // 10240
#define B_BYTES (BN * ROWB)     // 10240
#define STAGE (A_BYTES + B_BYTES)          // 20480
#define NSTAGE 3
#define GEMM_SMEM (NSTAGE * STAGE)         // 61440

// k_prep role split
#define NCVT_H ((B_ * S_ * H2_) / 2048)    // 16384 blocks
#define NCVT_W ((ATT_ * H2_) / 2048)       // 256 blocks
#define NHT    ((B_ * H2_) / 256)          // 256 blocks

// Scratch (device globals)
__device__ __half g_h16[(size_t)B_ * S_ * H2_];   // fp16 copy of h (64 MB)
__device__ __half g_w16[ATT_ * H2_];              // fp16 copy of w1_w[:, :1024]
__device__ float  g_ht_mean[B_ * H2_];
__device__ float  g_c[B_ * ATT_];
__device__ float  g_beta_part[4][B_ * S_];

// ---------------------------------------------------------------------------
__device__ __forceinline__ void cp16(uint32_t smem_dst, const void* gsrc) {
    asm volatile("cp.async.cg.shared.global [%0], [%1], 16;\n"
                 :: "r"(smem_dst), "l"(gsrc));
}
#define CP_COMMIT asm volatile("cp.async.commit_group;\n" ::: "memory")
#define CP_WAIT1  asm volatile("cp.async.wait_group 1;\n" ::: "memory")

__device__ __forceinline__ uint32_t smem_u32(const void* p) {
    uint32_t a;
    asm("{ .reg .u64 t; cvta.to.shared.u64 t, %1; cvt.u32.u64 %0, t; }"
        : "=r"(a) : "l"(p));
    return a;
}

__device__ __forceinline__ void mma_f16(float* d, const uint32_t* a,
                                        const uint32_t* b) {
    asm volatile(
        "mma.sync.aligned.m16n8k16.row.col.f32.f16.f16.f32 "
        "{%0,%1,%2,%3}, {%4,%5,%6,%7}, {%8,%9}, {%0,%1,%2,%3};\n"
        : "+f"(d[0]), "+f"(d[1]), "+f"(d[2]), "+f"(d[3])
        : "r"(a[0]), "r"(a[1]), "r"(a[2]), "r"(a[3]), "r"(b[0]), "r"(b[1]));
}

__device__ __forceinline__ void ldsm_x4(uint32_t& r0, uint32_t& r1,
                                        uint32_t& r2, uint32_t& r3,
                                        uint32_t addr) {
    asm volatile(
        "ldmatrix.sync.aligned.m8n8.x4.shared.b16 {%0,%1,%2,%3}, [%4];"
        : "=r"(r0), "=r"(r1), "=r"(r2), "=r"(r3) : "r"(addr));
}

__device__ __forceinline__ float tanh_hw(float x) {
    float t;
    asm("tanh.approx.f32 %0, %1;" : "=f"(t) : "f"(x));
    return t;
}

__device__ __forceinline__ uint4 cvt8(const float* src) {
    float4 f0 = *reinterpret_cast<const float4*>(src);
    float4 f1 = *reinterpret_cast<const float4*>(src + 4);
    __half2 a = __floats2half2_rn(f0.x, f0.y);
    __half2 b = __floats2half2_rn(f0.z, f0.w);
    __half2 c = __floats2half2_rn(f1.x, f1.y);
    __half2 d = __floats2half2_rn(f1.z, f1.w);
    uint4 v;
    v.x = *reinterpret_cast<uint32_t*>(&a);
    v.y = *reinterpret_cast<uint32_t*>(&b);
    v.z = *reinterpret_cast<uint32_t*>(&c);
    v.w = *reinterpret_cast<uint32_t*>(&d);
    return v;
}

// ---------------------------------------------------------------------------
// Fused prep: cvt h->fp16, cvt w1_w[:, :1024]->fp16, ht_mean. Role by block.
// ---------------------------------------------------------------------------
__global__ void k_prep(const float* __restrict__ h,
                       const float* __restrict__ w1_w,
                       const float* __restrict__ ht) {
    const int blk = blockIdx.x;
    if (blk < NCVT_H) {
        size_t i = ((size_t)blk * 256 + threadIdx.x) * 8;
        *reinterpret_cast<uint4*>(&g_h16[i]) = cvt8(h + i);
    } else if (blk < NCVT_H + NCVT_W) {
        size_t i = ((size_t)(blk - NCVT_H) * 256 + threadIdx.x) * 8;
        int row = (int)(i >> 10);
        int col = (int)(i & 1023);
        *reinterpret_cast<uint4*>(&g_w16[i]) =
            cvt8(w1_w + (size_t)row * WSTR_ + col);
    } else {
        int idx = (blk - NCVT_H - NCVT_W) * 256 + threadIdx.x;
        int b = idx >> 10;
        const float* p = ht + (size_t)b * T_ * H2_ + (idx & (H2_ - 1));
        float s = 0.f;
#pragma unroll
        for (int t = 0; t < T_; ++t) s += p[(size_t)t * H2_];
        g_ht_mean[idx] = s * (1.0f / T_);
    }
}

// ---------------------------------------------------------------------------
// c[b,a] = dot(ht_mean[b], w1_w[a,1024:]) + bias[a]
// grid (64 a-chunks, 8 b-chunks); 8 warps; warp owns a-row, computes all
// 8 batch dots in one pass (8 independent accumulators).
// ---------------------------------------------------------------------------
__global__ __launch_bounds__(256) void k_c(const float* __restrict__ w1_w,
                                           const float* __restrict__ w1_b) {
    __shared__ float sw[8][H2_];    // 32 KB: w rows
    __shared__ float shm[8][H2_];   // 32 KB: ht_mean rows
    const int a0 = blockIdx.x * 8;
    const int b0 = blockIdx.y * 8;
    const int tid = threadIdx.x;
    for (int i = tid; i < 8 * 256; i += 256) {
        int row = i >> 8, c4 = i & 255;
        reinterpret_cast<float4*>(sw[row])[c4] =
            *reinterpret_cast<const float4*>(
                w1_w + (size_t)(a0 + row) * WSTR_ + H2_ + c4 * 4);
        reinterpret_cast<float4*>(shm[row])[c4] =
            *reinterpret_cast<const float4*>(
                g_ht_mean + (b0 + row) * H2_ + c4 * 4);
    }
    __syncthreads();
    const int wid = tid >> 5, lane = tid & 31;
    const float bias = w1_b[a0 + wid];
    const float4* swv = reinterpret_cast<const float4*>(sw[wid]);

    float acc[8];
#pragma unroll
    for (int bi = 0; bi < 8; ++bi) acc[bi] = 0.f;

#pragma unroll
    for (int q = 0; q < 8; ++q) {
        float4 wv = swv[lane + q * 32];
#pragma unroll
        for (int bi = 0; bi < 8; ++bi) {
            float4 hv =
                reinterpret_cast<const float4*>(shm[bi])[lane + q * 32];
            acc[bi] += hv.x * wv.x + hv.y * wv.y + hv.z * wv.z + hv.w * wv.w;
        }
    }
#pragma unroll
    for (int bi = 0; bi < 8; ++bi) {
#pragma unroll
        for (int off = 16; off; off >>= 1)
            acc[bi] += __shfl_down_sync(0xffffffffu, acc[bi], off);
        if (lane == 0) g_c[(b0 + bi) * ATT_ + a0 + wid] = acc[bi] + bias;
    }
}

// ---------------------------------------------------------------------------
// Main fused GEMM (fp16 HMMA, fp32 accum), 128x128 CTA tile, 128 threads,
// 4 warps with 64x64 warp tiles, 3 CTAs/SM, pure cp.async, 3-stage ring.
// Prefetch of stage it+2 hoisted to right after the barrier.
// ---------------------------------------------------------------------------
__global__ __launch_bounds__(128, 3) void k_gemm_beta(
    const float* __restrict__ u_w)
{
    extern __shared__ char smem[];
    const uint32_t sb = smem_u32(smem);

    const int tid = threadIdx.x;
    const int lane = tid & 31;
    const int wid = tid >> 5;
    const int warp_m = wid >> 1;      // 0..1, 64 rows
    const int warp_n = wid & 1;       // 0..1, 64 cols
    const int r = lane >> 2;          // 0..7
    const int t = lane & 3;           // 0..3

    const int n0 = blockIdx.x * BN;
    const int m0 = blockIdx.y * BM;
    const int b_idx = m0 >> 9;

    // ldmatrix per-lane base offsets (bytes)
    const int lane7 = lane & 7;
    const int lg8 = (lane >> 3) & 1;
    const int lg16 = lane >> 4;
    const uint32_t a_off =
        (uint32_t)((warp_m * 64 + lg8 * 8 + lane7) * ROWB + lg16 * 16);
    const uint32_t b_off =
        (uint32_t)(A_BYTES + (warp_n * 64 + lg8 * 8 + lane7) * ROWB +
                   lg16 * 16);

    // cp.async addressing: 512 16B chunks per tile / 128 thr = 4 each
    const int crow = tid >> 2;
    const int cq = tid & 3;

    float acc[4][8][4];
#pragma unroll
    for (int i = 0; i < 4; ++i)
#pragma unroll
        for (int j = 0; j < 8; ++j)
#pragma unroll
            for (int k = 0; k < 4; ++k) acc[i][j][k] = 0.f;

    auto load_stage = [&](int it) {    // one commit group per call
        const uint32_t base = sb + (uint32_t)((it % 3) * STAGE);
        const int kb = it * BK;
#pragma unroll
        for (int s = 0; s < 4; ++s) {  // A
            int row = crow + s * 32;
            cp16(base + (uint32_t)(row * ROWB + cq * 16),
                 g_h16 + (size_t)(m0 + row) * H2_ + kb + cq * 8);
        }
#pragma unroll
        for (int s = 0; s < 4; ++s) {  // B
            int row = crow + s * 32;
            cp16(base + A_BYTES + (uint32_t)(row * ROWB + cq * 16),
                 g_w16 + (size_t)(n0 + row) * H2_ + kb + cq * 8);
        }
        CP_COMMIT;
    };

    load_stage(0);
    load_stage(1);

    for (int it = 0; it < NIT; ++it) {
        CP_WAIT1;                 // stage it landed (stage it+1 may pend)
        __syncthreads();

        // hoisted prefetch: slot (it+2)%3 == slot (it-1)%3, freed by barrier
        if (it + 2 < NIT) load_stage(it + 2);
        else CP_COMMIT;           // empty group keeps wait_group accounting

        const uint32_t sbase = sb + (uint32_t)((it % 3) * STAGE);
        const uint32_t abase = sbase + a_off;
        const uint32_t bbase = sbase + b_off;

#pragma unroll
        for (int ks = 0; ks < 2; ++ks) {
            uint32_t af[4][4], bf[8][2];
#pragma unroll
            for (int mf = 0; mf < 4; ++mf)
                ldsm_x4(af[mf][0], af[mf][1], af[mf][2], af[mf][3],
                        abase + mf * 1280 + ks * 32);
#pragma unroll
            for (int nfp = 0; nfp < 4; ++nfp)
                ldsm_x4(bf[2 * nfp][0], bf[2 * nfp + 1][0],
                        bf[2 * nfp][1], bf[2 * nfp + 1][1],
                        bbase + nfp * 1280 + ks * 32);
#pragma unroll
            for (int mf = 0; mf < 4; ++mf)
#pragma unroll
                for (int nf = 0; nf < 8; ++nf)
                    mma_f16(acc[mf][nf], af[mf], bf[nf]);
        }
    }

    // ---- fused epilogue ----
    float uv[8][2], cv[8][2];
#pragma unroll
    for (int nf = 0; nf < 8; ++nf)
#pragma unroll
        for (int j = 0; j < 2; ++j) {
            int n = n0 + warp_n * 64 + nf * 8 + t * 2 + j;
            uv[nf][j] = u_w[n];
            cv[nf][j] = g_c[b_idx * ATT_ + n];
        }

    float part[4][2];
#pragma unroll
    for (int mf = 0; mf < 4; ++mf)
#pragma unroll
        for (int half = 0; half < 2; ++half) {
            float p = 0.f;
#pragma unroll
            for (int nf = 0; nf < 8; ++nf)
#pragma unroll
                for (int j = 0; j < 2; ++j) {
                    float z = acc[mf][nf][half * 2 + j] + cv[nf][j];
                    p += uv[nf][j] * tanh_hw(z);
                }
            part[mf][half] = p;
        }

#pragma unroll
    for (int mf = 0; mf < 4; ++mf)
#pragma unroll
        for (int half = 0; half < 2; ++half) {
            float p = part[mf][half];
            p += __shfl_xor_sync(0xffffffffu, p, 1);
            p += __shfl_xor_sync(0xffffffffu, p, 2);
            part[mf][half] = p;
        }

    __syncthreads();
    float* red = reinterpret_cast<float*>(smem);   // [128][2]
    if (t == 0) {
#pragma unroll
        for (int mf = 0; mf < 4; ++mf)
#pragma unroll
            for (int half = 0; half < 2; ++half) {
                int row = warp_m * 64 + mf * 16 + half * 8 + r;
                red[row * 2 + warp_n] = part[mf][half];
            }
    }
    __syncthreads();
    if (tid < BM)
        g_beta_part[blockIdx.x][m0 + tid] = red[tid * 2] + red[tid * 2 + 1];
}

// ---------------------------------------------------------------------------
// Fused softmax + weighted sum, reading fp16 h copy. grid (4 d-chunks, 64 b).
// ---------------------------------------------------------------------------
__global__ __launch_bounds__(256) void k_out(const int* __restrict__ h_mask,
                                             float* __restrict__ out) {
    const int b = blockIdx.y;
    const int d0 = blockIdx.x * 256;
    const int tid = threadIdx.x;
    const int ds = tid & 63;
    const int ss = tid >> 6;

    __shared__ float salpha[S_];
    __shared__ float tmp[256];
    __shared__ float red[3][256];

    float beta[2];
#pragma unroll
    for (int k = 0; k < 2; ++k) {
        int s = tid + k * 256;
        int idx = b * S_ + s;
        float v = g_beta_part[0][idx] + g_beta_part[1][idx] +
                  g_beta_part[2][idx] + g_beta_part[3][idx];
        beta[k] = (h_mask[idx] != 0) ? v : -1e20f;
    }
    tmp[tid] = fmaxf(beta[0], beta[1]);
    __syncthreads();
#pragma unroll
    for (int off = 128; off; off >>= 1) {
        if (tid < off) tmp[tid] = fmaxf(tmp[tid], tmp[tid + off]);
        __syncthreads();
    }
    const float mx = tmp[0];
    __syncthreads();
    float e0 = __expf(beta[0] - mx);
    float e1 = __expf(beta[1] - mx);
    salpha[tid] = e0;
    salpha[tid + 256] = e1;
    tmp[tid] = e0 + e1;
    __syncthreads();
#pragma unroll
    for (int off = 128; off; off >>= 1) {
        if (tid < off) tmp[tid] += tmp[tid + off];
        __syncthreads();
    }
    const float inv = 1.0f / tmp[0];
    __syncthreads();

    float acc[4] = {0.f, 0.f, 0.f, 0.f};
    const __half* hp =
        g_h16 + ((size_t)b * S_ + ss * 128) * H2_ + d0 + ds * 4;
    const float* al = salpha + ss * 128;
#pragma unroll 8
    for (int s = 0; s < 128; ++s) {
        uint2 v = *reinterpret_cast<const uint2*>(hp + (size_t)s * H2_);
        float a = al[s];
        float2 p0 = __half22float2(*reinterpret_cast<__half2*>(&v.x));
        float2 p1 = __half22float2(*reinterpret_cast<__half2*>(&v.y));
        acc[0] += a * p0.x; acc[1] += a * p0.y;
        acc[2] += a * p1.x; acc[3] += a * p1.y;
    }
    if (ss) {
#pragma unroll
        for (int k = 0; k < 4; ++k) red[ss - 1][ds * 4 + k] = acc[k];
    }
    __syncthreads();
    if (ss == 0) {
#pragma unroll
        for (int k = 0; k < 4; ++k) {
            float v = acc[k] + red[0][ds * 4 + k] + red[1][ds * 4 + k] +
                      red[2][ds * 4 + k];
            out[b * H2_ + d0 + ds * 4 + k] = v * inv;
        }
    }
}

// ---------------------------------------------------------------------------
extern "C" void kernel_launch(void* const* d_in, const int* in_sizes, int n_in,
                              void* d_out, int out_size) {
    const float* h      = (const float*)d_in[0];
    const int*   h_mask = (const int*)  d_in[1];
    const float* ht     = (const float*)d_in[2];
    const float* w1_w   = (const float*)d_in[3];
    const float* w1_b   = (const float*)d_in[4];
    const float* u_w    = (const float*)d_in[5];
    float* out = (float*)d_out;

    cudaFuncSetAttribute(k_gemm_beta,
                         cudaFuncAttributeMaxDynamicSharedMemorySize,
                         GEMM_SMEM);

    k_prep<<<NCVT_H + NCVT_W + NHT, 256>>>(h, w1_w, ht);
    k_c<<<dim3(ATT_ / 8, B_ / 8), 256>>>(w1_w, w1_b);
    k_gemm_beta<<<dim3(ATT_ / BN, (B_ * S_) / BM), 128, GEMM_SMEM>>>(u_w);
    k_out<<<dim3(4, B_), 256>>>(h_mask, out);
}

// round 12
// speedup vs baseline: 1.0543x; 1.0543x over previous
#include <cuda_runtime.h>
#include <cuda_fp16.h>
#include <cstdint>

// Problem constants
#define B_    64
#define S_    512
#define T_    32
#define H2_   1024
#define ATT_  512
#define WSTR_ 2048

// GEMM tiling (fp16 mma.m16n8k16, fp32 accum)
#define BM 128
#define BN 128
#define BK 32
#define NIT (H2_ / BK)          // 32
#define ROWB 80                 // padded smem row bytes (conflict-free ldmatrix)
#define A_BYTES (BM * ROWB)     // 10240
#define B_BYTES (BN * ROWB)     // 10240
#define STAGE (A_BYTES + B_BYTES)          // 20480
#define NSTAGE 3
#define GEMM_SMEM (NSTAGE * STAGE)         // 61440

// k_prep role split
#define NCVT_H ((B_ * S_ * H2_) / 2048)    // 16384 blocks
#define NCVT_W ((ATT_ * H2_) / 2048)       // 256 blocks
#define NHT    ((B_ * H2_) / 256)          // 256 blocks

// Scratch (device globals)
__device__ __half g_h16[(size_t)B_ * S_ * H2_];   // fp16 copy of h (64 MB)
__device__ __half g_w16[ATT_ * H2_];              // fp16 copy of w1_w[:, :1024]
__device__ float  g_ht_mean[B_ * H2_];
__device__ float  g_c[B_ * ATT_];
__device__ float  g_beta_part[4][B_ * S_];

// ---------------------------------------------------------------------------
__device__ __forceinline__ void cp16(uint32_t smem_dst, const void* gsrc) {
    asm volatile("cp.async.cg.shared.global [%0], [%1], 16;\n"
                 :: "r"(smem_dst), "l"(gsrc));
}
#define CP_COMMIT asm volatile("cp.async.commit_group;\n" ::: "memory")
#define CP_WAIT1  asm volatile("cp.async.wait_group 1;\n" ::: "memory")

__device__ __forceinline__ uint32_t smem_u32(const void* p) {
    uint32_t a;
    asm("{ .reg .u64 t; cvta.to.shared.u64 t, %1; cvt.u32.u64 %0, t; }"
        : "=r"(a) : "l"(p));
    return a;
}

__device__ __forceinline__ void mma_f16(float* d, const uint32_t* a,
                                        const uint32_t* b) {
    asm volatile(
        "mma.sync.aligned.m16n8k16.row.col.f32.f16.f16.f32 "
        "{%0,%1,%2,%3}, {%4,%5,%6,%7}, {%8,%9}, {%0,%1,%2,%3};\n"
        : "+f"(d[0]), "+f"(d[1]), "+f"(d[2]), "+f"(d[3])
        : "r"(a[0]), "r"(a[1]), "r"(a[2]), "r"(a[3]), "r"(b[0]), "r"(b[1]));
}

__device__ __forceinline__ void ldsm_x4(uint32_t& r0, uint32_t& r1,
                                        uint32_t& r2, uint32_t& r3,
                                        uint32_t addr) {
    asm volatile(
        "ldmatrix.sync.aligned.m8n8.x4.shared.b16 {%0,%1,%2,%3}, [%4];"
        : "=r"(r0), "=r"(r1), "=r"(r2), "=r"(r3) : "r"(addr));
}

__device__ __forceinline__ float tanh_hw(float x) {
    float t;
    asm("tanh.approx.f32 %0, %1;" : "=f"(t) : "f"(x));
    return t;
}

__device__ __forceinline__ uint4 cvt8(const float* src) {
    float4 f0 = *reinterpret_cast<const float4*>(src);
    float4 f1 = *reinterpret_cast<const float4*>(src + 4);
    __half2 a = __floats2half2_rn(f0.x, f0.y);
    __half2 b = __floats2half2_rn(f0.z, f0.w);
    __half2 c = __floats2half2_rn(f1.x, f1.y);
    __half2 d = __floats2half2_rn(f1.z, f1.w);
    uint4 v;
    v.x = *reinterpret_cast<uint32_t*>(&a);
    v.y = *reinterpret_cast<uint32_t*>(&b);
    v.z = *reinterpret_cast<uint32_t*>(&c);
    v.w = *reinterpret_cast<uint32_t*>(&d);
    return v;
}

// ---------------------------------------------------------------------------
// Fused prep: cvt h->fp16, cvt w1_w[:, :1024]->fp16, ht_mean. Role by block.
// ---------------------------------------------------------------------------
__global__ void k_prep(const float* __restrict__ h,
                       const float* __restrict__ w1_w,
                       const float* __restrict__ ht) {
    const int blk = blockIdx.x;
    if (blk < NCVT_H) {
        size_t i = ((size_t)blk * 256 + threadIdx.x) * 8;
        *reinterpret_cast<uint4*>(&g_h16[i]) = cvt8(h + i);
    } else if (blk < NCVT_H + NCVT_W) {
        size_t i = ((size_t)(blk - NCVT_H) * 256 + threadIdx.x) * 8;
        int row = (int)(i >> 10);
        int col = (int)(i & 1023);
        *reinterpret_cast<uint4*>(&g_w16[i]) =
            cvt8(w1_w + (size_t)row * WSTR_ + col);
    } else {
        int idx = (blk - NCVT_H - NCVT_W) * 256 + threadIdx.x;
        int b = idx >> 10;
        const float* p = ht + (size_t)b * T_ * H2_ + (idx & (H2_ - 1));
        float s = 0.f;
#pragma unroll
        for (int t = 0; t < T_; ++t) s += p[(size_t)t * H2_];
        g_ht_mean[idx] = s * (1.0f / T_);
    }
}

// ---------------------------------------------------------------------------
// c[b,a] = dot(ht_mean[b], w1_w[a,1024:]) + bias[a]
// grid (64 a-chunks, 8 b-chunks); warp owns a-row, 8 batch dots in one pass.
// ---------------------------------------------------------------------------
__global__ __launch_bounds__(256) void k_c(const float* __restrict__ w1_w,
                                           const float* __restrict__ w1_b) {
    __shared__ float sw[8][H2_];    // 32 KB: w rows
    __shared__ float shm[8][H2_];   // 32 KB: ht_mean rows
    const int a0 = blockIdx.x * 8;
    const int b0 = blockIdx.y * 8;
    const int tid = threadIdx.x;
    for (int i = tid; i < 8 * 256; i += 256) {
        int row = i >> 8, c4 = i & 255;
        reinterpret_cast<float4*>(sw[row])[c4] =
            *reinterpret_cast<const float4*>(
                w1_w + (size_t)(a0 + row) * WSTR_ + H2_ + c4 * 4);
        reinterpret_cast<float4*>(shm[row])[c4] =
            *reinterpret_cast<const float4*>(
                g_ht_mean + (b0 + row) * H2_ + c4 * 4);
    }
    __syncthreads();
    const int wid = tid >> 5, lane = tid & 31;
    const float bias = w1_b[a0 + wid];
    const float4* swv = reinterpret_cast<const float4*>(sw[wid]);

    float acc[8];
#pragma unroll
    for (int bi = 0; bi < 8; ++bi) acc[bi] = 0.f;

#pragma unroll
    for (int q = 0; q < 8; ++q) {
        float4 wv = swv[lane + q * 32];
#pragma unroll
        for (int bi = 0; bi < 8; ++bi) {
            float4 hv =
                reinterpret_cast<const float4*>(shm[bi])[lane + q * 32];
            acc[bi] += hv.x * wv.x + hv.y * wv.y + hv.z * wv.z + hv.w * wv.w;
        }
    }
#pragma unroll
    for (int bi = 0; bi < 8; ++bi) {
#pragma unroll
        for (int off = 16; off; off >>= 1)
            acc[bi] += __shfl_down_sync(0xffffffffu, acc[bi], off);
        if (lane == 0) g_c[(b0 + bi) * ATT_ + a0 + wid] = acc[bi] + bias;
    }
}

// ---------------------------------------------------------------------------
// Main fused GEMM (fp16 HMMA, fp32 accum), 128x128 CTA tile, 128 threads,
// 4 warps with 64x64 warp tiles, 3 CTAs/SM, pure cp.async, 3-stage ring.
// Prefetch issued AFTER the MMA block (post-R11 revert: keeping cp.async
// issue off the barrier->LDSM critical path is worth ~10us).
// ---------------------------------------------------------------------------
__global__ __launch_bounds__(128, 3) void k_gemm_beta(
    const float* __restrict__ u_w)
{
    extern __shared__ char smem[];
    const uint32_t sb = smem_u32(smem);

    const int tid = threadIdx.x;
    const int lane = tid & 31;
    const int wid = tid >> 5;
    const int warp_m = wid >> 1;      // 0..1, 64 rows
    const int warp_n = wid & 1;       // 0..1, 64 cols
    const int r = lane >> 2;          // 0..7
    const int t = lane & 3;           // 0..3

    const int n0 = blockIdx.x * BN;
    const int m0 = blockIdx.y * BM;
    const int b_idx = m0 >> 9;

    // ldmatrix per-lane base offsets (bytes)
    const int lane7 = lane & 7;
    const int lg8 = (lane >> 3) & 1;
    const int lg16 = lane >> 4;
    const uint32_t a_off =
        (uint32_t)((warp_m * 64 + lg8 * 8 + lane7) * ROWB + lg16 * 16);
    const uint32_t b_off =
        (uint32_t)(A_BYTES + (warp_n * 64 + lg8 * 8 + lane7) * ROWB +
                   lg16 * 16);

    // cp.async addressing: 512 16B chunks per tile / 128 thr = 4 each
    const int crow = tid >> 2;
    const int cq = tid & 3;

    float acc[4][8][4];
#pragma unroll
    for (int i = 0; i < 4; ++i)
#pragma unroll
        for (int j = 0; j < 8; ++j)
#pragma unroll
            for (int k = 0; k < 4; ++k) acc[i][j][k] = 0.f;

    auto load_stage = [&](int it) {    // one commit group per call
        const uint32_t base = sb + (uint32_t)((it % 3) * STAGE);
        const int kb = it * BK;
#pragma unroll
        for (int s = 0; s < 4; ++s) {  // A
            int row = crow + s * 32;
            cp16(base + (uint32_t)(row * ROWB + cq * 16),
                 g_h16 + (size_t)(m0 + row) * H2_ + kb + cq * 8);
        }
#pragma unroll
        for (int s = 0; s < 4; ++s) {  // B
            int row = crow + s * 32;
            cp16(base + A_BYTES + (uint32_t)(row * ROWB + cq * 16),
                 g_w16 + (size_t)(n0 + row) * H2_ + kb + cq * 8);
        }
        CP_COMMIT;
    };

    load_stage(0);
    load_stage(1);

    for (int it = 0; it < NIT; ++it) {
        CP_WAIT1;                 // stage it landed (stage it+1 may pend)
        __syncthreads();

        const uint32_t sbase = sb + (uint32_t)((it % 3) * STAGE);
        const uint32_t abase = sbase + a_off;
        const uint32_t bbase = sbase + b_off;

#pragma unroll
        for (int ks = 0; ks < 2; ++ks) {
            uint32_t af[4][4], bf[8][2];
#pragma unroll
            for (int mf = 0; mf < 4; ++mf)
                ldsm_x4(af[mf][0], af[mf][1], af[mf][2], af[mf][3],
                        abase + mf * 1280 + ks * 32);
#pragma unroll
            for (int nfp = 0; nfp < 4; ++nfp)
                ldsm_x4(bf[2 * nfp][0], bf[2 * nfp + 1][0],
                        bf[2 * nfp][1], bf[2 * nfp + 1][1],
                        bbase + nfp * 1280 + ks * 32);
#pragma unroll
            for (int mf = 0; mf < 4; ++mf)
#pragma unroll
                for (int nf = 0; nf < 8; ++nf)
                    mma_f16(acc[mf][nf], af[mf], bf[nf]);
        }

        if (it + 2 < NIT) load_stage(it + 2);
        else CP_COMMIT;           // empty group keeps wait_group accounting
    }

    // ---- fused epilogue ----
    float uv[8][2], cv[8][2];
#pragma unroll
    for (int nf = 0; nf < 8; ++nf)
#pragma unroll
        for (int j = 0; j < 2; ++j) {
            int n = n0 + warp_n * 64 + nf * 8 + t * 2 + j;
            uv[nf][j] = u_w[n];
            cv[nf][j] = g_c[b_idx * ATT_ + n];
        }

    float part[4][2];
#pragma unroll
    for (int mf = 0; mf < 4; ++mf)
#pragma unroll
        for (int half = 0; half < 2; ++half) {
            float p = 0.f;
#pragma unroll
            for (int nf = 0; nf < 8; ++nf)
#pragma unroll
                for (int j = 0; j < 2; ++j) {
                    float z = acc[mf][nf][half * 2 + j] + cv[nf][j];
                    p += uv[nf][j] * tanh_hw(z);
                }
            part[mf][half] = p;
        }

#pragma unroll
    for (int mf = 0; mf < 4; ++mf)
#pragma unroll
        for (int half = 0; half < 2; ++half) {
            float p = part[mf][half];
            p += __shfl_xor_sync(0xffffffffu, p, 1);
            p += __shfl_xor_sync(0xffffffffu, p, 2);
            part[mf][half] = p;
        }

    __syncthreads();
    float* red = reinterpret_cast<float*>(smem);   // [128][2]
    if (t == 0) {
#pragma unroll
        for (int mf = 0; mf < 4; ++mf)
#pragma unroll
            for (int half = 0; half < 2; ++half) {
                int row = warp_m * 64 + mf * 16 + half * 8 + r;
                red[row * 2 + warp_n] = part[mf][half];
            }
    }
    __syncthreads();
    if (tid < BM)
        g_beta_part[blockIdx.x][m0 + tid] = red[tid * 2] + red[tid * 2 + 1];
}

// ---------------------------------------------------------------------------
// Fused softmax + weighted sum, fp16 h copy, uint4 loads.
// grid (4 d-chunks, 64 b); ds = tid&31 owns 8 halves, ss = tid>>5 covers 64 s.
// ---------------------------------------------------------------------------
__global__ __launch_bounds__(256) void k_out(const int* __restrict__ h_mask,
                                             float* __restrict__ out) {
    const int b = blockIdx.y;
    const int d0 = blockIdx.x * 256;
    const int tid = threadIdx.x;
    const int ds = tid & 31;
    const int ss = tid >> 5;

    __shared__ float salpha[S_];
    __shared__ float tmp[256];
    __shared__ float red[7][256];

    // --- softmax (each thread handles s = tid and tid+256) ---
    float beta[2];
#pragma unroll
    for (int k = 0; k < 2; ++k) {
        int s = tid + k * 256;
        int idx = b * S_ + s;
        float v = g_beta_part[0][idx] + g_beta_part[1][idx] +
                  g_beta_part[2][idx] + g_beta_part[3][idx];
        beta[k] = (h_mask[idx] != 0) ? v : -1e20f;
    }
    tmp[tid] = fmaxf(beta[0], beta[1]);
    __syncthreads();
#pragma unroll
    for (int off = 128; off; off >>= 1) {
        if (tid < off) tmp[tid] = fmaxf(tmp[tid], tmp[tid + off]);
        __syncthreads();
    }
    const float mx = tmp[0];
    __syncthreads();
    float e0 = __expf(beta[0] - mx);
    float e1 = __expf(beta[1] - mx);
    salpha[tid] = e0;
    salpha[tid + 256] = e1;
    tmp[tid] = e0 + e1;
    __syncthreads();
#pragma unroll
    for (int off = 128; off; off >>= 1) {
        if (tid < off) tmp[tid] += tmp[tid + off];
        __syncthreads();
    }
    const float inv = 1.0f / tmp[0];
    __syncthreads();

    // --- weighted sum over this thread's 64-s slice, 8 d per thread ---
    float acc[8];
#pragma unroll
    for (int k = 0; k < 8; ++k) acc[k] = 0.f;
    const __half* hp =
        g_h16 + ((size_t)b * S_ + ss * 64) * H2_ + d0 + ds * 8;
    const float* al = salpha + ss * 64;
#pragma unroll 4
    for (int s = 0; s < 64; ++s) {
        uint4 v = *reinterpret_cast<const uint4*>(hp + (size_t)s * H2_);
        float a = al[s];
        float2 p0 = __half22float2(*reinterpret_cast<__half2*>(&v.x));
        float2 p1 = __half22float2(*reinterpret_cast<__half2*>(&v.y));
        float2 p2 = __half22float2(*reinterpret_cast<__half2*>(&v.z));
        float2 p3 = __half22float2(*reinterpret_cast<__half2*>(&v.w));
        acc[0] += a * p0.x; acc[1] += a * p0.y;
        acc[2] += a * p1.x; acc[3] += a * p1.y;
        acc[4] += a * p2.x; acc[5] += a * p2.y;
        acc[6] += a * p3.x; acc[7] += a * p3.y;
    }
    if (ss) {
#pragma unroll
        for (int k = 0; k < 8; ++k) red[ss - 1][ds * 8 + k] = acc[k];
    }
    __syncthreads();
    if (ss == 0) {
#pragma unroll
        for (int k = 0; k < 8; ++k) {
            float v = acc[k];
#pragma unroll
            for (int sl = 0; sl < 7; ++sl) v += red[sl][ds * 8 + k];
            out[b * H2_ + d0 + ds * 8 + k] = v * inv;
        }
    }
}

// ---------------------------------------------------------------------------
extern "C" void kernel_launch(void* const* d_in, const int* in_sizes, int n_in,
                              void* d_out, int out_size) {
    const float* h      = (const float*)d_in[0];
    const int*   h_mask = (const int*)  d_in[1];
    const float* ht     = (const float*)d_in[2];
    const float* w1_w   = (const float*)d_in[3];
    const float* w1_b   = (const float*)d_in[4];
    const float* u_w    = (const float*)d_in[5];
    float* out = (float*)d_out;

    cudaFuncSetAttribute(k_gemm_beta,
                         cudaFuncAttributeMaxDynamicSharedMemorySize,
                         GEMM_SMEM);

    k_prep<<<NCVT_H + NCVT_W + NHT, 256>>>(h, w1_w, ht);
    k_c<<<dim3(ATT_ / 8, B_ / 8), 256>>>(w1_w, w1_b);
    k_gemm_beta<<<dim3(ATT_ / BN, (B_ * S_) / BM), 128, GEMM_SMEM>>>(u_w);
    k_out<<<dim3(4, B_), 256>>>(h_mask, out);
}

// round 13
// speedup vs baseline: 1.0908x; 1.0347x over previous
#include <cuda_runtime.h>
#include <cuda_fp16.h>
#include <cstdint>

// Problem constants
#define B_    64
#define S_    512
#define T_    32
#define H2_   1024
#define ATT_  512
#define WSTR_ 2048

// GEMM tiling (fp16 mma.m16n8k16, fp32 accum)
#define BM 128
#define BN 128
#define BK 32
#define NIT (H2_ / BK)          // 32
#define ROWB 80                 // padded smem row bytes (conflict-free ldmatrix)
#define A_BYTES (BM * ROWB)     // 10240
#define B_BYTES (BN * ROWB)     // 10240
#define STAGE (A_BYTES + B_BYTES)          // 20480
#define NSTAGE 3
#define GEMM_SMEM (NSTAGE * STAGE)         // 61440

// k_prep role split
#define NCVT_H ((B_ * S_ * H2_) / 2048)    // 16384 blocks
#define NCVT_W ((ATT_ * H2_) / 2048)       // 256 blocks
#define NHT    ((B_ * H2_) / 256)          // 256 blocks

// Scratch (device globals)
__device__ __half g_h16[(size_t)B_ * S_ * H2_];   // fp16 copy of h (64 MB)
__device__ __half g_w16[ATT_ * H2_];              // fp16 copy of w1_w[:, :1024]
__device__ float  g_ht_mean[B_ * H2_];
__device__ float  g_c[B_ * ATT_];
__device__ float  g_beta_part[4][B_ * S_];

// ---------------------------------------------------------------------------
__device__ __forceinline__ void cp16(uint32_t smem_dst, const void* gsrc) {
    asm volatile("cp.async.cg.shared.global [%0], [%1], 16;\n"
                 :: "r"(smem_dst), "l"(gsrc));
}
#define CP_COMMIT asm volatile("cp.async.commit_group;\n" ::: "memory")
#define CP_WAIT1  asm volatile("cp.async.wait_group 1;\n" ::: "memory")

__device__ __forceinline__ uint32_t smem_u32(const void* p) {
    uint32_t a;
    asm("{ .reg .u64 t; cvta.to.shared.u64 t, %1; cvt.u32.u64 %0, t; }"
        : "=r"(a) : "l"(p));
    return a;
}

__device__ __forceinline__ void mma_f16(float* d, const uint32_t* a,
                                        const uint32_t* b) {
    asm volatile(
        "mma.sync.aligned.m16n8k16.row.col.f32.f16.f16.f32 "
        "{%0,%1,%2,%3}, {%4,%5,%6,%7}, {%8,%9}, {%0,%1,%2,%3};\n"
        : "+f"(d[0]), "+f"(d[1]), "+f"(d[2]), "+f"(d[3])
        : "r"(a[0]), "r"(a[1]), "r"(a[2]), "r"(a[3]), "r"(b[0]), "r"(b[1]));
}

__device__ __forceinline__ void ldsm_x4(uint32_t& r0, uint32_t& r1,
                                        uint32_t& r2, uint32_t& r3,
                                        uint32_t addr) {
    asm volatile(
        "ldmatrix.sync.aligned.m8n8.x4.shared.b16 {%0,%1,%2,%3}, [%4];"
        : "=r"(r0), "=r"(r1), "=r"(r2), "=r"(r3) : "r"(addr));
}

__device__ __forceinline__ float tanh_hw(float x) {
    float t;
    asm("tanh.approx.f32 %0, %1;" : "=f"(t) : "f"(x));
    return t;
}

__device__ __forceinline__ uint4 cvt8(const float* src) {
    float4 f0 = *reinterpret_cast<const float4*>(src);
    float4 f1 = *reinterpret_cast<const float4*>(src + 4);
    __half2 a = __floats2half2_rn(f0.x, f0.y);
    __half2 b = __floats2half2_rn(f0.z, f0.w);
    __half2 c = __floats2half2_rn(f1.x, f1.y);
    __half2 d = __floats2half2_rn(f1.z, f1.w);
    uint4 v;
    v.x = *reinterpret_cast<uint32_t*>(&a);
    v.y = *reinterpret_cast<uint32_t*>(&b);
    v.z = *reinterpret_cast<uint32_t*>(&c);
    v.w = *reinterpret_cast<uint32_t*>(&d);
    return v;
}

// ---------------------------------------------------------------------------
// Fused prep: cvt h->fp16, cvt w1_w[:, :1024]->fp16, ht_mean. Role by block.
// ---------------------------------------------------------------------------
__global__ void k_prep(const float* __restrict__ h,
                       const float* __restrict__ w1_w,
                       const float* __restrict__ ht) {
    const int blk = blockIdx.x;
    if (blk < NCVT_H) {
        size_t i = ((size_t)blk * 256 + threadIdx.x) * 8;
        *reinterpret_cast<uint4*>(&g_h16[i]) = cvt8(h + i);
    } else if (blk < NCVT_H + NCVT_W) {
        size_t i = ((size_t)(blk - NCVT_H) * 256 + threadIdx.x) * 8;
        int row = (int)(i >> 10);
        int col = (int)(i & 1023);
        *reinterpret_cast<uint4*>(&g_w16[i]) =
            cvt8(w1_w + (size_t)row * WSTR_ + col);
    } else {
        int idx = (blk - NCVT_H - NCVT_W) * 256 + threadIdx.x;
        int b = idx >> 10;
        const float* p = ht + (size_t)b * T_ * H2_ + (idx & (H2_ - 1));
        float s = 0.f;
#pragma unroll
        for (int t = 0; t < T_; ++t) s += p[(size_t)t * H2_];
        g_ht_mean[idx] = s * (1.0f / T_);
    }
}

// ---------------------------------------------------------------------------
// c[b,a] = dot(ht_mean[b], w1_w[a,1024:]) + bias[a]
// grid (64 a-chunks, 8 b-chunks); warp owns a-row, 8 batch dots in one pass.
// ---------------------------------------------------------------------------
__global__ __launch_bounds__(256) void k_c(const float* __restrict__ w1_w,
                                           const float* __restrict__ w1_b) {
    __shared__ float sw[8][H2_];    // 32 KB: w rows
    __shared__ float shm[8][H2_];   // 32 KB: ht_mean rows
    const int a0 = blockIdx.x * 8;
    const int b0 = blockIdx.y * 8;
    const int tid = threadIdx.x;
    for (int i = tid; i < 8 * 256; i += 256) {
        int row = i >> 8, c4 = i & 255;
        reinterpret_cast<float4*>(sw[row])[c4] =
            *reinterpret_cast<const float4*>(
                w1_w + (size_t)(a0 + row) * WSTR_ + H2_ + c4 * 4);
        reinterpret_cast<float4*>(shm[row])[c4] =
            *reinterpret_cast<const float4*>(
                g_ht_mean + (b0 + row) * H2_ + c4 * 4);
    }
    __syncthreads();
    const int wid = tid >> 5, lane = tid & 31;
    const float bias = w1_b[a0 + wid];
    const float4* swv = reinterpret_cast<const float4*>(sw[wid]);

    float acc[8];
#pragma unroll
    for (int bi = 0; bi < 8; ++bi) acc[bi] = 0.f;

#pragma unroll
    for (int q = 0; q < 8; ++q) {
        float4 wv = swv[lane + q * 32];
#pragma unroll
        for (int bi = 0; bi < 8; ++bi) {
            float4 hv =
                reinterpret_cast<const float4*>(shm[bi])[lane + q * 32];
            acc[bi] += hv.x * wv.x + hv.y * wv.y + hv.z * wv.z + hv.w * wv.w;
        }
    }
#pragma unroll
    for (int bi = 0; bi < 8; ++bi) {
#pragma unroll
        for (int off = 16; off; off >>= 1)
            acc[bi] += __shfl_down_sync(0xffffffffu, acc[bi], off);
        if (lane == 0) g_c[(b0 + bi) * ATT_ + a0 + wid] = acc[bi] + bias;
    }
}

// ---------------------------------------------------------------------------
// Main fused GEMM (fp16 HMMA, fp32 accum), 128x128 CTA tile, 128 threads,
// 4 warps with 64x64 warp tiles, 3 CTAs/SM, pure cp.async, 3-stage ring.
// Prefetch issued AFTER the MMA block (R11 post-mortem: hoisting cp.async
// between barrier and LDSM costs ~10us; keep it here).
// ---------------------------------------------------------------------------
__global__ __launch_bounds__(128, 3) void k_gemm_beta(
    const float* __restrict__ u_w)
{
    extern __shared__ char smem[];
    const uint32_t sb = smem_u32(smem);

    const int tid = threadIdx.x;
    const int lane = tid & 31;
    const int wid = tid >> 5;
    const int warp_m = wid >> 1;      // 0..1, 64 rows
    const int warp_n = wid & 1;       // 0..1, 64 cols
    const int r = lane >> 2;          // 0..7
    const int t = lane & 3;           // 0..3

    const int n0 = blockIdx.x * BN;
    const int m0 = blockIdx.y * BM;
    const int b_idx = m0 >> 9;

    // ldmatrix per-lane base offsets (bytes)
    const int lane7 = lane & 7;
    const int lg8 = (lane >> 3) & 1;
    const int lg16 = lane >> 4;
    const uint32_t a_off =
        (uint32_t)((warp_m * 64 + lg8 * 8 + lane7) * ROWB + lg16 * 16);
    const uint32_t b_off =
        (uint32_t)(A_BYTES + (warp_n * 64 + lg8 * 8 + lane7) * ROWB +
                   lg16 * 16);

    // cp.async addressing: 512 16B chunks per tile / 128 thr = 4 each
    const int crow = tid >> 2;
    const int cq = tid & 3;

    float acc[4][8][4];
#pragma unroll
    for (int i = 0; i < 4; ++i)
#pragma unroll
        for (int j = 0; j < 8; ++j)
#pragma unroll
            for (int k = 0; k < 4; ++k) acc[i][j][k] = 0.f;

    auto load_stage = [&](int it) {    // one commit group per call
        const uint32_t base = sb + (uint32_t)((it % 3) * STAGE);
        const int kb = it * BK;
#pragma unroll
        for (int s = 0; s < 4; ++s) {  // A
            int row = crow + s * 32;
            cp16(base + (uint32_t)(row * ROWB + cq * 16),
                 g_h16 + (size_t)(m0 + row) * H2_ + kb + cq * 8);
        }
#pragma unroll
        for (int s = 0; s < 4; ++s) {  // B
            int row = crow + s * 32;
            cp16(base + A_BYTES + (uint32_t)(row * ROWB + cq * 16),
                 g_w16 + (size_t)(n0 + row) * H2_ + kb + cq * 8);
        }
        CP_COMMIT;
    };

    load_stage(0);
    load_stage(1);

    for (int it = 0; it < NIT; ++it) {
        CP_WAIT1;                 // stage it landed (stage it+1 may pend)
        __syncthreads();

        const uint32_t sbase = sb + (uint32_t)((it % 3) * STAGE);
        const uint32_t abase = sbase + a_off;
        const uint32_t bbase = sbase + b_off;

#pragma unroll
        for (int ks = 0; ks < 2; ++ks) {
            uint32_t af[4][4], bf[8][2];
#pragma unroll
            for (int mf = 0; mf < 4; ++mf)
                ldsm_x4(af[mf][0], af[mf][1], af[mf][2], af[mf][3],
                        abase + mf * 1280 + ks * 32);
#pragma unroll
            for (int nfp = 0; nfp < 4; ++nfp)
                ldsm_x4(bf[2 * nfp][0], bf[2 * nfp + 1][0],
                        bf[2 * nfp][1], bf[2 * nfp + 1][1],
                        bbase + nfp * 1280 + ks * 32);
#pragma unroll
            for (int mf = 0; mf < 4; ++mf)
#pragma unroll
                for (int nf = 0; nf < 8; ++nf)
                    mma_f16(acc[mf][nf], af[mf], bf[nf]);
        }

        if (it + 2 < NIT) load_stage(it + 2);
        else CP_COMMIT;           // empty group keeps wait_group accounting
    }

    // ---- fused epilogue ----
    float uv[8][2], cv[8][2];
#pragma unroll
    for (int nf = 0; nf < 8; ++nf)
#pragma unroll
        for (int j = 0; j < 2; ++j) {
            int n = n0 + warp_n * 64 + nf * 8 + t * 2 + j;
            uv[nf][j] = u_w[n];
            cv[nf][j] = g_c[b_idx * ATT_ + n];
        }

    float part[4][2];
#pragma unroll
    for (int mf = 0; mf < 4; ++mf)
#pragma unroll
        for (int half = 0; half < 2; ++half) {
            float p = 0.f;
#pragma unroll
            for (int nf = 0; nf < 8; ++nf)
#pragma unroll
                for (int j = 0; j < 2; ++j) {
                    float z = acc[mf][nf][half * 2 + j] + cv[nf][j];
                    p += uv[nf][j] * tanh_hw(z);
                }
            part[mf][half] = p;
        }

#pragma unroll
    for (int mf = 0; mf < 4; ++mf)
#pragma unroll
        for (int half = 0; half < 2; ++half) {
            float p = part[mf][half];
            p += __shfl_xor_sync(0xffffffffu, p, 1);
            p += __shfl_xor_sync(0xffffffffu, p, 2);
            part[mf][half] = p;
        }

    __syncthreads();
    float* red = reinterpret_cast<float*>(smem);   // [128][2]
    if (t == 0) {
#pragma unroll
        for (int mf = 0; mf < 4; ++mf)
#pragma unroll
            for (int half = 0; half < 2; ++half) {
                int row = warp_m * 64 + mf * 16 + half * 8 + r;
                red[row * 2 + warp_n] = part[mf][half];
            }
    }
    __syncthreads();
    if (tid < BM)
        g_beta_part[blockIdx.x][m0 + tid] = red[tid * 2] + red[tid * 2 + 1];
}

// ---------------------------------------------------------------------------
// Fused softmax + weighted sum, fp16 h copy, uint4 loads, 512 threads.
// grid (4 d-chunks, 64 b); ds = tid&31 owns 8 halves, ss = tid>>5 covers
// 16 slices of 32 s each (2x warps in flight vs R12 -> 2x MLP).
// ---------------------------------------------------------------------------
__global__ __launch_bounds__(512) void k_out(const int* __restrict__ h_mask,
                                             float* __restrict__ out) {
    const int b = blockIdx.y;
    const int d0 = blockIdx.x * 256;
    const int tid = threadIdx.x;
    const int ds = tid & 31;
    const int ss = tid >> 5;

    __shared__ float salpha[S_];
    __shared__ float tmp[512];
    __shared__ float red[15][256];

    // --- softmax (one s per thread) ---
    const int idx = b * S_ + tid;
    float beta = g_beta_part[0][idx] + g_beta_part[1][idx] +
                 g_beta_part[2][idx] + g_beta_part[3][idx];
    beta = (h_mask[idx] != 0) ? beta : -1e20f;
    tmp[tid] = beta;
    __syncthreads();
#pragma unroll
    for (int off = 256; off; off >>= 1) {
        if (tid < off) tmp[tid] = fmaxf(tmp[tid], tmp[tid + off]);
        __syncthreads();
    }
    const float mx = tmp[0];
    __syncthreads();
    float e = __expf(beta - mx);
    salpha[tid] = e;
    tmp[tid] = e;
    __syncthreads();
#pragma unroll
    for (int off = 256; off; off >>= 1) {
        if (tid < off) tmp[tid] += tmp[tid + off];
        __syncthreads();
    }
    const float inv = 1.0f / tmp[0];
    __syncthreads();

    // --- weighted sum over this thread's 32-s slice, 8 d per thread ---
    float acc[8];
#pragma unroll
    for (int k = 0; k < 8; ++k) acc[k] = 0.f;
    const __half* hp =
        g_h16 + ((size_t)b * S_ + ss * 32) * H2_ + d0 + ds * 8;
    const float* al = salpha + ss * 32;
#pragma unroll 4
    for (int s = 0; s < 32; ++s) {
        uint4 v = *reinterpret_cast<const uint4*>(hp + (size_t)s * H2_);
        float a = al[s];
        float2 p0 = __half22float2(*reinterpret_cast<__half2*>(&v.x));
        float2 p1 = __half22float2(*reinterpret_cast<__half2*>(&v.y));
        float2 p2 = __half22float2(*reinterpret_cast<__half2*>(&v.z));
        float2 p3 = __half22float2(*reinterpret_cast<__half2*>(&v.w));
        acc[0] += a * p0.x; acc[1] += a * p0.y;
        acc[2] += a * p1.x; acc[3] += a * p1.y;
        acc[4] += a * p2.x; acc[5] += a * p2.y;
        acc[6] += a * p3.x; acc[7] += a * p3.y;
    }
    if (ss) {
#pragma unroll
        for (int k = 0; k < 8; ++k) red[ss - 1][ds * 8 + k] = acc[k];
    }
    __syncthreads();
    if (ss == 0) {
#pragma unroll
        for (int k = 0; k < 8; ++k) {
            float v = acc[k];
#pragma unroll
            for (int sl = 0; sl < 15; ++sl) v += red[sl][ds * 8 + k];
            out[b * H2_ + d0 + ds * 8 + k] = v * inv;
        }
    }
}

// ---------------------------------------------------------------------------
extern "C" void kernel_launch(void* const* d_in, const int* in_sizes, int n_in,
                              void* d_out, int out_size) {
    const float* h      = (const float*)d_in[0];
    const int*   h_mask = (const int*)  d_in[1];
    const float* ht     = (const float*)d_in[2];
    const float* w1_w   = (const float*)d_in[3];
    const float* w1_b   = (const float*)d_in[4];
    const float* u_w    = (const float*)d_in[5];
    float* out = (float*)d_out;

    cudaFuncSetAttribute(k_gemm_beta,
                         cudaFuncAttributeMaxDynamicSharedMemorySize,
                         GEMM_SMEM);

    k_prep<<<NCVT_H + NCVT_W + NHT, 256>>>(h, w1_w, ht);
    k_c<<<dim3(ATT_ / 8, B_ / 8), 256>>>(w1_w, w1_b);
    k_gemm_beta<<<dim3(ATT_ / BN, (B_ * S_) / BM), 128, GEMM_SMEM>>>(u_w);
    k_out<<<dim3(4, B_), 512>>>(h_mask, out);
}

// round 14
// speedup vs baseline: 1.1107x; 1.0183x over previous
#include <cuda_runtime.h>
#include <cuda_fp16.h>
#include <cstdint>

// Problem constants
#define B_    64
#define S_    512
#define T_    32
#define H2_   1024
#define ATT_  512
#define WSTR_ 2048

// GEMM tiling (fp16 mma.m16n8k16, fp32 accum)
#define BM 128
#define BN 128
#define BK 32
#define NIT (H2_ / BK)          // 32
#define ROWB 80                 // padded smem row bytes (conflict-free ldmatrix)
#define A_BYTES (BM * ROWB)     // 10240
#define B_BYTES (BN * ROWB)     // 10240
#define STAGE (A_BYTES + B_BYTES)          // 20480
#define NSTAGE 3
#define GEMM_SMEM (NSTAGE * STAGE)         // 61440

// k_prep role split
#define NCVT_H ((B_ * S_ * H2_) / 2048)    // 16384 blocks
#define NCVT_W ((ATT_ * H2_) / 2048)       // 256 blocks
#define NHT    ((B_ * H2_) / 256)          // 256 blocks

// Scratch (device globals)
__device__ __half g_h16[(size_t)B_ * S_ * H2_];   // fp16 copy of h (64 MB)
__device__ __half g_w16[ATT_ * H2_];              // fp16 copy of w1_w[:, :1024]
__device__ float  g_ht_mean[B_ * H2_];
__device__ float  g_c[B_ * ATT_];
__device__ float  g_beta_part[4][B_ * S_];

// ---------------------------------------------------------------------------
__device__ __forceinline__ void cp16(uint32_t smem_dst, const void* gsrc) {
    asm volatile("cp.async.cg.shared.global [%0], [%1], 16;\n"
                 :: "r"(smem_dst), "l"(gsrc));
}
#define CP_COMMIT asm volatile("cp.async.commit_group;\n" ::: "memory")
#define CP_WAIT1  asm volatile("cp.async.wait_group 1;\n" ::: "memory")

__device__ __forceinline__ uint32_t smem_u32(const void* p) {
    uint32_t a;
    asm("{ .reg .u64 t; cvta.to.shared.u64 t, %1; cvt.u32.u64 %0, t; }"
        : "=r"(a) : "l"(p));
    return a;
}

__device__ __forceinline__ void mma_f16(float* d, const uint32_t* a,
                                        const uint32_t* b) {
    asm volatile(
        "mma.sync.aligned.m16n8k16.row.col.f32.f16.f16.f32 "
        "{%0,%1,%2,%3}, {%4,%5,%6,%7}, {%8,%9}, {%0,%1,%2,%3};\n"
        : "+f"(d[0]), "+f"(d[1]), "+f"(d[2]), "+f"(d[3])
        : "r"(a[0]), "r"(a[1]), "r"(a[2]), "r"(a[3]), "r"(b[0]), "r"(b[1]));
}

__device__ __forceinline__ void ldsm_x4(uint32_t& r0, uint32_t& r1,
                                        uint32_t& r2, uint32_t& r3,
                                        uint32_t addr) {
    asm volatile(
        "ldmatrix.sync.aligned.m8n8.x4.shared.b16 {%0,%1,%2,%3}, [%4];"
        : "=r"(r0), "=r"(r1), "=r"(r2), "=r"(r3) : "r"(addr));
}

__device__ __forceinline__ float tanh_hw(float x) {
    float t;
    asm("tanh.approx.f32 %0, %1;" : "=f"(t) : "f"(x));
    return t;
}

__device__ __forceinline__ uint4 cvt8(const float* src) {
    float4 f0 = *reinterpret_cast<const float4*>(src);
    float4 f1 = *reinterpret_cast<const float4*>(src + 4);
    __half2 a = __floats2half2_rn(f0.x, f0.y);
    __half2 b = __floats2half2_rn(f0.z, f0.w);
    __half2 c = __floats2half2_rn(f1.x, f1.y);
    __half2 d = __floats2half2_rn(f1.z, f1.w);
    uint4 v;
    v.x = *reinterpret_cast<uint32_t*>(&a);
    v.y = *reinterpret_cast<uint32_t*>(&b);
    v.z = *reinterpret_cast<uint32_t*>(&c);
    v.w = *reinterpret_cast<uint32_t*>(&d);
    return v;
}

// ---------------------------------------------------------------------------
// Fused prep: cvt h->fp16, cvt w1_w[:, :1024]->fp16, ht_mean. Role by block.
// ---------------------------------------------------------------------------
__global__ void k_prep(const float* __restrict__ h,
                       const float* __restrict__ w1_w,
                       const float* __restrict__ ht) {
    const int blk = blockIdx.x;
    if (blk < NCVT_H) {
        size_t i = ((size_t)blk * 256 + threadIdx.x) * 8;
        *reinterpret_cast<uint4*>(&g_h16[i]) = cvt8(h + i);
    } else if (blk < NCVT_H + NCVT_W) {
        size_t i = ((size_t)(blk - NCVT_H) * 256 + threadIdx.x) * 8;
        int row = (int)(i >> 10);
        int col = (int)(i & 1023);
        *reinterpret_cast<uint4*>(&g_w16[i]) =
            cvt8(w1_w + (size_t)row * WSTR_ + col);
    } else {
        int idx = (blk - NCVT_H - NCVT_W) * 256 + threadIdx.x;
        int b = idx >> 10;
        const float* p = ht + (size_t)b * T_ * H2_ + (idx & (H2_ - 1));
        float s = 0.f;
#pragma unroll
        for (int t = 0; t < T_; ++t) s += p[(size_t)t * H2_];
        g_ht_mean[idx] = s * (1.0f / T_);
    }
}

// ---------------------------------------------------------------------------
// c[b,a] = dot(ht_mean[b], w1_w[a,1024:]) + bias[a]
// grid (64 a-chunks, 8 b-chunks); warp owns a-row, 8 batch dots in one pass.
// ---------------------------------------------------------------------------
__global__ __launch_bounds__(256) void k_c(const float* __restrict__ w1_w,
                                           const float* __restrict__ w1_b) {
    __shared__ float sw[8][H2_];    // 32 KB: w rows
    __shared__ float shm[8][H2_];   // 32 KB: ht_mean rows
    const int a0 = blockIdx.x * 8;
    const int b0 = blockIdx.y * 8;
    const int tid = threadIdx.x;
    for (int i = tid; i < 8 * 256; i += 256) {
        int row = i >> 8, c4 = i & 255;
        reinterpret_cast<float4*>(sw[row])[c4] =
            *reinterpret_cast<const float4*>(
                w1_w + (size_t)(a0 + row) * WSTR_ + H2_ + c4 * 4);
        reinterpret_cast<float4*>(shm[row])[c4] =
            *reinterpret_cast<const float4*>(
                g_ht_mean + (b0 + row) * H2_ + c4 * 4);
    }
    __syncthreads();
    const int wid = tid >> 5, lane = tid & 31;
    const float bias = w1_b[a0 + wid];
    const float4* swv = reinterpret_cast<const float4*>(sw[wid]);

    float acc[8];
#pragma unroll
    for (int bi = 0; bi < 8; ++bi) acc[bi] = 0.f;

#pragma unroll
    for (int q = 0; q < 8; ++q) {
        float4 wv = swv[lane + q * 32];
#pragma unroll
        for (int bi = 0; bi < 8; ++bi) {
            float4 hv =
                reinterpret_cast<const float4*>(shm[bi])[lane + q * 32];
            acc[bi] += hv.x * wv.x + hv.y * wv.y + hv.z * wv.z + hv.w * wv.w;
        }
    }
#pragma unroll
    for (int bi = 0; bi < 8; ++bi) {
#pragma unroll
        for (int off = 16; off; off >>= 1)
            acc[bi] += __shfl_down_sync(0xffffffffu, acc[bi], off);
        if (lane == 0) g_c[(b0 + bi) * ATT_ + a0 + wid] = acc[bi] + bias;
    }
}

// ---------------------------------------------------------------------------
// Main fused GEMM (fp16 HMMA, fp32 accum), 128x128 CTA tile, 128 threads,
// 4 warps with 64x64 warp tiles, 3 CTAs/SM, pure cp.async, 3-stage ring.
// Prefetch issued AFTER the MMA block (R11 post-mortem: hoisting cp.async
// between barrier and LDSM costs ~10us; keep it here).
// ---------------------------------------------------------------------------
__global__ __launch_bounds__(128, 3) void k_gemm_beta(
    const float* __restrict__ u_w)
{
    extern __shared__ char smem[];
    const uint32_t sb = smem_u32(smem);

    const int tid = threadIdx.x;
    const int lane = tid & 31;
    const int wid = tid >> 5;
    const int warp_m = wid >> 1;      // 0..1, 64 rows
    const int warp_n = wid & 1;       // 0..1, 64 cols
    const int r = lane >> 2;          // 0..7
    const int t = lane & 3;           // 0..3

    const int n0 = blockIdx.x * BN;
    const int m0 = blockIdx.y * BM;
    const int b_idx = m0 >> 9;

    // ldmatrix per-lane base offsets (bytes)
    const int lane7 = lane & 7;
    const int lg8 = (lane >> 3) & 1;
    const int lg16 = lane >> 4;
    const uint32_t a_off =
        (uint32_t)((warp_m * 64 + lg8 * 8 + lane7) * ROWB + lg16 * 16);
    const uint32_t b_off =
        (uint32_t)(A_BYTES + (warp_n * 64 + lg8 * 8 + lane7) * ROWB +
                   lg16 * 16);

    // cp.async addressing: 512 16B chunks per tile / 128 thr = 4 each
    const int crow = tid >> 2;
    const int cq = tid & 3;

    float acc[4][8][4];
#pragma unroll
    for (int i = 0; i < 4; ++i)
#pragma unroll
        for (int j = 0; j < 8; ++j)
#pragma unroll
            for (int k = 0; k < 4; ++k) acc[i][j][k] = 0.f;

    auto load_stage = [&](int it) {    // one commit group per call
        const uint32_t base = sb + (uint32_t)((it % 3) * STAGE);
        const int kb = it * BK;
#pragma unroll
        for (int s = 0; s < 4; ++s) {  // A
            int row = crow + s * 32;
            cp16(base + (uint32_t)(row * ROWB + cq * 16),
                 g_h16 + (size_t)(m0 + row) * H2_ + kb + cq * 8);
        }
#pragma unroll
        for (int s = 0; s < 4; ++s) {  // B
            int row = crow + s * 32;
            cp16(base + A_BYTES + (uint32_t)(row * ROWB + cq * 16),
                 g_w16 + (size_t)(n0 + row) * H2_ + kb + cq * 8);
        }
        CP_COMMIT;
    };

    load_stage(0);
    load_stage(1);

    for (int it = 0; it < NIT; ++it) {
        CP_WAIT1;                 // stage it landed (stage it+1 may pend)
        __syncthreads();

        const uint32_t sbase = sb + (uint32_t)((it % 3) * STAGE);
        const uint32_t abase = sbase + a_off;
        const uint32_t bbase = sbase + b_off;

#pragma unroll
        for (int ks = 0; ks < 2; ++ks) {
            uint32_t af[4][4], bf[8][2];
#pragma unroll
            for (int mf = 0; mf < 4; ++mf)
                ldsm_x4(af[mf][0], af[mf][1], af[mf][2], af[mf][3],
                        abase + mf * 1280 + ks * 32);
#pragma unroll
            for (int nfp = 0; nfp < 4; ++nfp)
                ldsm_x4(bf[2 * nfp][0], bf[2 * nfp + 1][0],
                        bf[2 * nfp][1], bf[2 * nfp + 1][1],
                        bbase + nfp * 1280 + ks * 32);
#pragma unroll
            for (int mf = 0; mf < 4; ++mf)
#pragma unroll
                for (int nf = 0; nf < 8; ++nf)
                    mma_f16(acc[mf][nf], af[mf], bf[nf]);
        }

        if (it + 2 < NIT) load_stage(it + 2);
        else CP_COMMIT;           // empty group keeps wait_group accounting
    }

    // ---- fused epilogue ----
    float uv[8][2], cv[8][2];
#pragma unroll
    for (int nf = 0; nf < 8; ++nf)
#pragma unroll
        for (int j = 0; j < 2; ++j) {
            int n = n0 + warp_n * 64 + nf * 8 + t * 2 + j;
            uv[nf][j] = u_w[n];
            cv[nf][j] = g_c[b_idx * ATT_ + n];
        }

    float part[4][2];
#pragma unroll
    for (int mf = 0; mf < 4; ++mf)
#pragma unroll
        for (int half = 0; half < 2; ++half) {
            float p = 0.f;
#pragma unroll
            for (int nf = 0; nf < 8; ++nf)
#pragma unroll
                for (int j = 0; j < 2; ++j) {
                    float z = acc[mf][nf][half * 2 + j] + cv[nf][j];
                    p += uv[nf][j] * tanh_hw(z);
                }
            part[mf][half] = p;
        }

#pragma unroll
    for (int mf = 0; mf < 4; ++mf)
#pragma unroll
        for (int half = 0; half < 2; ++half) {
            float p = part[mf][half];
            p += __shfl_xor_sync(0xffffffffu, p, 1);
            p += __shfl_xor_sync(0xffffffffu, p, 2);
            part[mf][half] = p;
        }

    __syncthreads();
    float* red = reinterpret_cast<float*>(smem);   // [128][2]
    if (t == 0) {
#pragma unroll
        for (int mf = 0; mf < 4; ++mf)
#pragma unroll
            for (int half = 0; half < 2; ++half) {
                int row = warp_m * 64 + mf * 16 + half * 8 + r;
                red[row * 2 + warp_n] = part[mf][half];
            }
    }
    __syncthreads();
    if (tid < BM)
        g_beta_part[blockIdx.x][m0 + tid] = red[tid * 2] + red[tid * 2 + 1];
}

// ---------------------------------------------------------------------------
// Fused softmax + weighted sum, fp16 h copy, uint4 loads.
// grid (8 d-chunks of 128, 64 b), 256 threads: ds = tid&15 owns 8 halves,
// ss = tid>>4 covers 16 slices of 32 s. 512 blocks -> ~3.4 blocks/SM
// (R13 post-mortem: 256 blocks was the occupancy limiter, not threads).
// ---------------------------------------------------------------------------
__global__ __launch_bounds__(256) void k_out(const int* __restrict__ h_mask,
                                             float* __restrict__ out) {
    const int b = blockIdx.y;
    const int d0 = blockIdx.x * 128;
    const int tid = threadIdx.x;
    const int ds = tid & 15;
    const int ss = tid >> 4;

    __shared__ float salpha[S_];
    __shared__ float tmp[256];
    __shared__ float red[15][128];

    // --- softmax (each thread handles s = tid and tid+256) ---
    float beta[2];
#pragma unroll
    for (int k = 0; k < 2; ++k) {
        int s = tid + k * 256;
        int idx = b * S_ + s;
        float v = g_beta_part[0][idx] + g_beta_part[1][idx] +
                  g_beta_part[2][idx] + g_beta_part[3][idx];
        beta[k] = (h_mask[idx] != 0) ? v : -1e20f;
    }
    tmp[tid] = fmaxf(beta[0], beta[1]);
    __syncthreads();
#pragma unroll
    for (int off = 128; off; off >>= 1) {
        if (tid < off) tmp[tid] = fmaxf(tmp[tid], tmp[tid + off]);
        __syncthreads();
    }
    const float mx = tmp[0];
    __syncthreads();
    float e0 = __expf(beta[0] - mx);
    float e1 = __expf(beta[1] - mx);
    salpha[tid] = e0;
    salpha[tid + 256] = e1;
    tmp[tid] = e0 + e1;
    __syncthreads();
#pragma unroll
    for (int off = 128; off; off >>= 1) {
        if (tid < off) tmp[tid] += tmp[tid + off];
        __syncthreads();
    }
    const float inv = 1.0f / tmp[0];
    __syncthreads();

    // --- weighted sum over this thread's 32-s slice, 8 d per thread ---
    float acc[8];
#pragma unroll
    for (int k = 0; k < 8; ++k) acc[k] = 0.f;
    const __half* hp =
        g_h16 + ((size_t)b * S_ + ss * 32) * H2_ + d0 + ds * 8;
    const float* al = salpha + ss * 32;
#pragma unroll 4
    for (int s = 0; s < 32; ++s) {
        uint4 v = *reinterpret_cast<const uint4*>(hp + (size_t)s * H2_);
        float a = al[s];
        float2 p0 = __half22float2(*reinterpret_cast<__half2*>(&v.x));
        float2 p1 = __half22float2(*reinterpret_cast<__half2*>(&v.y));
        float2 p2 = __half22float2(*reinterpret_cast<__half2*>(&v.z));
        float2 p3 = __half22float2(*reinterpret_cast<__half2*>(&v.w));
        acc[0] += a * p0.x; acc[1] += a * p0.y;
        acc[2] += a * p1.x; acc[3] += a * p1.y;
        acc[4] += a * p2.x; acc[5] += a * p2.y;
        acc[6] += a * p3.x; acc[7] += a * p3.y;
    }
    if (ss) {
#pragma unroll
        for (int k = 0; k < 8; ++k) red[ss - 1][ds * 8 + k] = acc[k];
    }
    __syncthreads();
    if (ss == 0) {
#pragma unroll
        for (int k = 0; k < 8; ++k) {
            float v = acc[k];
#pragma unroll
            for (int sl = 0; sl < 15; ++sl) v += red[sl][ds * 8 + k];
            out[b * H2_ + d0 + ds * 8 + k] = v * inv;
        }
    }
}

// ---------------------------------------------------------------------------
extern "C" void kernel_launch(void* const* d_in, const int* in_sizes, int n_in,
                              void* d_out, int out_size) {
    const float* h      = (const float*)d_in[0];
    const int*   h_mask = (const int*)  d_in[1];
    const float* ht     = (const float*)d_in[2];
    const float* w1_w   = (const float*)d_in[3];
    const float* w1_b   = (const float*)d_in[4];
    const float* u_w    = (const float*)d_in[5];
    float* out = (float*)d_out;

    cudaFuncSetAttribute(k_gemm_beta,
                         cudaFuncAttributeMaxDynamicSharedMemorySize,
                         GEMM_SMEM);

    k_prep<<<NCVT_H + NCVT_W + NHT, 256>>>(h, w1_w, ht);
    k_c<<<dim3(ATT_ / 8, B_ / 8), 256>>>(w1_w, w1_b);
    k_gemm_beta<<<dim3(ATT_ / BN, (B_ * S_) / BM), 128, GEMM_SMEM>>>(u_w);
    k_out<<<dim3(8, B_), 256>>>(h_mask, out);
}

// round 15
// speedup vs baseline: 1.2957x; 1.1665x over previous
#include <cuda_runtime.h>
#include <cuda_fp16.h>
#include <cstdint>

// Problem constants
#define B_    64
#define S_    512
#define T_    32
#define H2_   1024
#define ATT_  512
#define WSTR_ 2048

// GEMM tiling (fp16 mma.m16n8k16, fp32 accum)
#define BM 128
#define BN 128
#define BK 32
#define NIT (H2_ / BK)          // 32
#define ROWB 80                 // padded smem row bytes (conflict-free ldmatrix)
#define A_BYTES (BM * ROWB)     // 10240
#define B_BYTES (BN * ROWB)     // 10240
#define STAGE (A_BYTES + B_BYTES)          // 20480
#define NSTAGE 3
#define GEMM_SMEM (NSTAGE * STAGE)         // 61440

// k_prep role split
#define NGATH (B_ * S_)                    // 32768 gather blocks (1 row each)
#define NCVT_W ((ATT_ * H2_) / 2048)       // 256 blocks
#define NHT    ((B_ * H2_) / 256)          // 256 blocks

// Scratch (device globals)
__device__ __half g_h16[(size_t)B_ * S_ * H2_];   // compacted fp16 h (64 MB)
__device__ __half g_w16[ATT_ * H2_];              // fp16 copy of w1_w[:, :1024]
__device__ float  g_ht_mean[B_ * H2_];
__device__ float  g_c[B_ * ATT_];
__device__ float  g_beta_part[4][B_ * S_];
__device__ int    g_sidx[B_ * S_];                // compacted j -> original s
__device__ int    g_nv[B_];                       // valid count per batch

// ---------------------------------------------------------------------------
__device__ __forceinline__ void cp16(uint32_t smem_dst, const void* gsrc) {
    asm volatile("cp.async.cg.shared.global [%0], [%1], 16;\n"
                 :: "r"(smem_dst), "l"(gsrc));
}
#define CP_COMMIT asm volatile("cp.async.commit_group;\n" ::: "memory")
#define CP_WAIT1  asm volatile("cp.async.wait_group 1;\n" ::: "memory")

__device__ __forceinline__ uint32_t smem_u32(const void* p) {
    uint32_t a;
    asm("{ .reg .u64 t; cvta.to.shared.u64 t, %1; cvt.u32.u64 %0, t; }"
        : "=r"(a) : "l"(p));
    return a;
}

__device__ __forceinline__ void mma_f16(float* d, const uint32_t* a,
                                        const uint32_t* b) {
    asm volatile(
        "mma.sync.aligned.m16n8k16.row.col.f32.f16.f16.f32 "
        "{%0,%1,%2,%3}, {%4,%5,%6,%7}, {%8,%9}, {%0,%1,%2,%3};\n"
        : "+f"(d[0]), "+f"(d[1]), "+f"(d[2]), "+f"(d[3])
        : "r"(a[0]), "r"(a[1]), "r"(a[2]), "r"(a[3]), "r"(b[0]), "r"(b[1]));
}

__device__ __forceinline__ void ldsm_x4(uint32_t& r0, uint32_t& r1,
                                        uint32_t& r2, uint32_t& r3,
                                        uint32_t addr) {
    asm volatile(
        "ldmatrix.sync.aligned.m8n8.x4.shared.b16 {%0,%1,%2,%3}, [%4];"
        : "=r"(r0), "=r"(r1), "=r"(r2), "=r"(r3) : "r"(addr));
}

__device__ __forceinline__ float tanh_hw(float x) {
    float t;
    asm("tanh.approx.f32 %0, %1;" : "=f"(t) : "f"(x));
    return t;
}

__device__ __forceinline__ uint4 cvt8(const float* src) {
    float4 f0 = *reinterpret_cast<const float4*>(src);
    float4 f1 = *reinterpret_cast<const float4*>(src + 4);
    __half2 a = __floats2half2_rn(f0.x, f0.y);
    __half2 b = __floats2half2_rn(f0.z, f0.w);
    __half2 c = __floats2half2_rn(f1.x, f1.y);
    __half2 d = __floats2half2_rn(f1.z, f1.w);
    uint4 v;
    v.x = *reinterpret_cast<uint32_t*>(&a);
    v.y = *reinterpret_cast<uint32_t*>(&b);
    v.z = *reinterpret_cast<uint32_t*>(&c);
    v.w = *reinterpret_cast<uint32_t*>(&d);
    return v;
}

// ---------------------------------------------------------------------------
// Mask compaction: per batch, prefix-scan h_mask -> g_sidx (valid s list),
// g_nv (count). Masked rows' beta is discarded by the reference (exp(-1e20)
// underflows to exactly 0 in fp32), so all downstream work runs in compacted
// j-space and never returns to s-space.
// ---------------------------------------------------------------------------
__global__ void k_mask(const int* __restrict__ h_mask) {
    const int b = blockIdx.x;
    const int s = threadIdx.x;
    __shared__ int sc[S_];
    int v = (h_mask[b * S_ + s] != 0) ? 1 : 0;
    sc[s] = v;
    __syncthreads();
#pragma unroll
    for (int off = 1; off < S_; off <<= 1) {
        int add = (s >= off) ? sc[s - off] : 0;
        __syncthreads();
        sc[s] += add;
        __syncthreads();
    }
    if (v) g_sidx[b * S_ + sc[s] - 1] = s;
    if (s == S_ - 1) g_nv[b] = sc[S_ - 1];
}

// ---------------------------------------------------------------------------
// Fused prep: gather-convert valid h rows (compacted, zero-pad to 128
// boundary), cvt w1_w[:, :1024] -> fp16, ht_mean. Role by block.
// ---------------------------------------------------------------------------
__global__ void k_prep(const float* __restrict__ h,
                       const float* __restrict__ w1_w,
                       const float* __restrict__ ht) {
    const int blk = blockIdx.x;
    const int tid = threadIdx.x;
    if (blk < NGATH) {
        const int b = blk >> 9;
        const int j = blk & 511;
        const int nv = g_nv[b];
        __half* dst = g_h16 + ((size_t)b * S_ + j) * H2_ + tid * 4;
        if (j < nv) {
            const int s = g_sidx[b * S_ + j];
            float4 f = *reinterpret_cast<const float4*>(
                h + ((size_t)b * S_ + s) * H2_ + tid * 4);
            __half2 lo = __floats2half2_rn(f.x, f.y);
            __half2 hi = __floats2half2_rn(f.z, f.w);
            uint2 v;
            v.x = *reinterpret_cast<uint32_t*>(&lo);
            v.y = *reinterpret_cast<uint32_t*>(&hi);
            *reinterpret_cast<uint2*>(dst) = v;
        } else if (j < ((nv + 127) & ~127)) {
            *reinterpret_cast<uint2*>(dst) = make_uint2(0u, 0u);
        }
    } else if (blk < NGATH + NCVT_W) {
        size_t i = ((size_t)(blk - NGATH) * 256 + tid) * 8;
        int row = (int)(i >> 10);
        int col = (int)(i & 1023);
        *reinterpret_cast<uint4*>(&g_w16[i]) =
            cvt8(w1_w + (size_t)row * WSTR_ + col);
    } else {
        int idx = (blk - NGATH - NCVT_W) * 256 + tid;
        int b = idx >> 10;
        const float* p = ht + (size_t)b * T_ * H2_ + (idx & (H2_ - 1));
        float s = 0.f;
#pragma unroll
        for (int t = 0; t < T_; ++t) s += p[(size_t)t * H2_];
        g_ht_mean[idx] = s * (1.0f / T_);
    }
}

// ---------------------------------------------------------------------------
// c[b,a] = dot(ht_mean[b], w1_w[a,1024:]) + bias[a]
// grid (64 a-chunks, 8 b-chunks); warp owns a-row, 8 batch dots in one pass.
// ---------------------------------------------------------------------------
__global__ __launch_bounds__(256) void k_c(const float* __restrict__ w1_w,
                                           const float* __restrict__ w1_b) {
    __shared__ float sw[8][H2_];    // 32 KB: w rows
    __shared__ float shm[8][H2_];   // 32 KB: ht_mean rows
    const int a0 = blockIdx.x * 8;
    const int b0 = blockIdx.y * 8;
    const int tid = threadIdx.x;
    for (int i = tid; i < 8 * 256; i += 256) {
        int row = i >> 8, c4 = i & 255;
        reinterpret_cast<float4*>(sw[row])[c4] =
            *reinterpret_cast<const float4*>(
                w1_w + (size_t)(a0 + row) * WSTR_ + H2_ + c4 * 4);
        reinterpret_cast<float4*>(shm[row])[c4] =
            *reinterpret_cast<const float4*>(
                g_ht_mean + (b0 + row) * H2_ + c4 * 4);
    }
    __syncthreads();
    const int wid = tid >> 5, lane = tid & 31;
    const float bias = w1_b[a0 + wid];
    const float4* swv = reinterpret_cast<const float4*>(sw[wid]);

    float acc[8];
#pragma unroll
    for (int bi = 0; bi < 8; ++bi) acc[bi] = 0.f;

#pragma unroll
    for (int q = 0; q < 8; ++q) {
        float4 wv = swv[lane + q * 32];
#pragma unroll
        for (int bi = 0; bi < 8; ++bi) {
            float4 hv =
                reinterpret_cast<const float4*>(shm[bi])[lane + q * 32];
            acc[bi] += hv.x * wv.x + hv.y * wv.y + hv.z * wv.z + hv.w * wv.w;
        }
    }
#pragma unroll
    for (int bi = 0; bi < 8; ++bi) {
#pragma unroll
        for (int off = 16; off; off >>= 1)
            acc[bi] += __shfl_down_sync(0xffffffffu, acc[bi], off);
        if (lane == 0) g_c[(b0 + bi) * ATT_ + a0 + wid] = acc[bi] + bias;
    }
}

// ---------------------------------------------------------------------------
// Main fused GEMM (fp16 HMMA, fp32 accum), 128x128 CTA tile, 128 threads,
// 4 warps with 64x64 warp tiles, 3 CTAs/SM, pure cp.async, 3-stage ring.
// Runs in compacted j-space; tiles entirely past nv[b] exit immediately.
// Prefetch issued AFTER the MMA block (R11 post-mortem: hoisting cp.async
// between barrier and LDSM costs ~10us; keep it here).
// ---------------------------------------------------------------------------
__global__ __launch_bounds__(128, 3) void k_gemm_beta(
    const float* __restrict__ u_w)
{
    extern __shared__ char smem[];
    const uint32_t sb = smem_u32(smem);

    const int tid = threadIdx.x;
    const int lane = tid & 31;
    const int wid = tid >> 5;
    const int warp_m = wid >> 1;      // 0..1, 64 rows
    const int warp_n = wid & 1;       // 0..1, 64 cols
    const int r = lane >> 2;          // 0..7
    const int t = lane & 3;           // 0..3

    const int n0 = blockIdx.x * BN;
    const int m0 = blockIdx.y * BM;
    const int b_idx = m0 >> 9;

    // compacted-space early exit: whole tile is padding -> no work
    if ((m0 & 511) >= g_nv[b_idx]) return;

    // ldmatrix per-lane base offsets (bytes)
    const int lane7 = lane & 7;
    const int lg8 = (lane >> 3) & 1;
    const int lg16 = lane >> 4;
    const uint32_t a_off =
        (uint32_t)((warp_m * 64 + lg8 * 8 + lane7) * ROWB + lg16 * 16);
    const uint32_t b_off =
        (uint32_t)(A_BYTES + (warp_n * 64 + lg8 * 8 + lane7) * ROWB +
                   lg16 * 16);

    // cp.async addressing: 512 16B chunks per tile / 128 thr = 4 each
    const int crow = tid >> 2;
    const int cq = tid & 3;

    float acc[4][8][4];
#pragma unroll
    for (int i = 0; i < 4; ++i)
#pragma unroll
        for (int j = 0; j < 8; ++j)
#pragma unroll
            for (int k = 0; k < 4; ++k) acc[i][j][k] = 0.f;

    auto load_stage = [&](int it) {    // one commit group per call
        const uint32_t base = sb + (uint32_t)((it % 3) * STAGE);
        const int kb = it * BK;
#pragma unroll
        for (int s = 0; s < 4; ++s) {  // A
            int row = crow + s * 32;
            cp16(base + (uint32_t)(row * ROWB + cq * 16),
                 g_h16 + (size_t)(m0 + row) * H2_ + kb + cq * 8);
        }
#pragma unroll
        for (int s = 0; s < 4; ++s) {  // B
            int row = crow + s * 32;
            cp16(base + A_BYTES + (uint32_t)(row * ROWB + cq * 16),
                 g_w16 + (size_t)(n0 + row) * H2_ + kb + cq * 8);
        }
        CP_COMMIT;
    };

    load_stage(0);
    load_stage(1);

    for (int it = 0; it < NIT; ++it) {
        CP_WAIT1;                 // stage it landed (stage it+1 may pend)
        __syncthreads();

        const uint32_t sbase = sb + (uint32_t)((it % 3) * STAGE);
        const uint32_t abase = sbase + a_off;
        const uint32_t bbase = sbase + b_off;

#pragma unroll
        for (int ks = 0; ks < 2; ++ks) {
            uint32_t af[4][4], bf[8][2];
#pragma unroll
            for (int mf = 0; mf < 4; ++mf)
                ldsm_x4(af[mf][0], af[mf][1], af[mf][2], af[mf][3],
                        abase + mf * 1280 + ks * 32);
#pragma unroll
            for (int nfp = 0; nfp < 4; ++nfp)
                ldsm_x4(bf[2 * nfp][0], bf[2 * nfp + 1][0],
                        bf[2 * nfp][1], bf[2 * nfp + 1][1],
                        bbase + nfp * 1280 + ks * 32);
#pragma unroll
            for (int mf = 0; mf < 4; ++mf)
#pragma unroll
                for (int nf = 0; nf < 8; ++nf)
                    mma_f16(acc[mf][nf], af[mf], bf[nf]);
        }

        if (it + 2 < NIT) load_stage(it + 2);
        else CP_COMMIT;           // empty group keeps wait_group accounting
    }

    // ---- fused epilogue ----
    float uv[8][2], cv[8][2];
#pragma unroll
    for (int nf = 0; nf < 8; ++nf)
#pragma unroll
        for (int j = 0; j < 2; ++j) {
            int n = n0 + warp_n * 64 + nf * 8 + t * 2 + j;
            uv[nf][j] = u_w[n];
            cv[nf][j] = g_c[b_idx * ATT_ + n];
        }

    float part[4][2];
#pragma unroll
    for (int mf = 0; mf < 4; ++mf)
#pragma unroll
        for (int half = 0; half < 2; ++half) {
            float p = 0.f;
#pragma unroll
            for (int nf = 0; nf < 8; ++nf)
#pragma unroll
                for (int j = 0; j < 2; ++j) {
                    float z = acc[mf][nf][half * 2 + j] + cv[nf][j];
                    p += uv[nf][j] * tanh_hw(z);
                }
            part[mf][half] = p;
        }

#pragma unroll
    for (int mf = 0; mf < 4; ++mf)
#pragma unroll
        for (int half = 0; half < 2; ++half) {
            float p = part[mf][half];
            p += __shfl_xor_sync(0xffffffffu, p, 1);
            p += __shfl_xor_sync(0xffffffffu, p, 2);
            part[mf][half] = p;
        }

    __syncthreads();
    float* red = reinterpret_cast<float*>(smem);   // [128][2]
    if (t == 0) {
#pragma unroll
        for (int mf = 0; mf < 4; ++mf)
#pragma unroll
            for (int half = 0; half < 2; ++half) {
                int row = warp_m * 64 + mf * 16 + half * 8 + r;
                red[row * 2 + warp_n] = part[mf][half];
            }
    }
    __syncthreads();
    if (tid < BM)
        g_beta_part[blockIdx.x][m0 + tid] = red[tid * 2] + red[tid * 2 + 1];
}

// ---------------------------------------------------------------------------
// Fused softmax + weighted sum in compacted j-space, fp16 h copy, uint4 loads.
// grid (8 d-chunks of 128, 64 b), 256 threads: ds = tid&15 owns 8 halves,
// ss = tid>>4 covers 16 slices of 32 j. Slices fully past nv are skipped.
// ---------------------------------------------------------------------------
__global__ __launch_bounds__(256) void k_out(float* __restrict__ out) {
    const int b = blockIdx.y;
    const int d0 = blockIdx.x * 128;
    const int tid = threadIdx.x;
    const int ds = tid & 15;
    const int ss = tid >> 4;
    const int nv = g_nv[b];

    __shared__ float salpha[S_];
    __shared__ float tmp[256];
    __shared__ float red[15][128];

    // --- softmax over compacted j (j >= nv excluded; exact vs reference
    //     since masked exp(-1e20 - mx) underflows to 0 in fp32) ---
    float beta[2];
#pragma unroll
    for (int k = 0; k < 2; ++k) {
        int j = tid + k * 256;
        int idx = b * S_ + j;
        float v = g_beta_part[0][idx] + g_beta_part[1][idx] +
                  g_beta_part[2][idx] + g_beta_part[3][idx];
        beta[k] = (j < nv) ? v : -1e20f;
    }
    tmp[tid] = fmaxf(beta[0], beta[1]);
    __syncthreads();
#pragma unroll
    for (int off = 128; off; off >>= 1) {
        if (tid < off) tmp[tid] = fmaxf(tmp[tid], tmp[tid + off]);
        __syncthreads();
    }
    const float mx = tmp[0];
    __syncthreads();
    float e0 = __expf(beta[0] - mx);
    float e1 = __expf(beta[1] - mx);
    salpha[tid] = e0;
    salpha[tid + 256] = e1;
    tmp[tid] = e0 + e1;
    __syncthreads();
#pragma unroll
    for (int off = 128; off; off >>= 1) {
        if (tid < off) tmp[tid] += tmp[tid + off];
        __syncthreads();
    }
    const float inv = 1.0f / tmp[0];
    __syncthreads();

    // --- weighted sum over this thread's 32-j slice, 8 d per thread ---
    float acc[8];
#pragma unroll
    for (int k = 0; k < 8; ++k) acc[k] = 0.f;
    if (ss * 32 < nv) {       // rows past nv are zero-padded; whole-slice skip
        const __half* hp =
            g_h16 + ((size_t)b * S_ + ss * 32) * H2_ + d0 + ds * 8;
        const float* al = salpha + ss * 32;
#pragma unroll 4
        for (int s = 0; s < 32; ++s) {
            uint4 v = *reinterpret_cast<const uint4*>(hp + (size_t)s * H2_);
            float a = al[s];
            float2 p0 = __half22float2(*reinterpret_cast<__half2*>(&v.x));
            float2 p1 = __half22float2(*reinterpret_cast<__half2*>(&v.y));
            float2 p2 = __half22float2(*reinterpret_cast<__half2*>(&v.z));
            float2 p3 = __half22float2(*reinterpret_cast<__half2*>(&v.w));
            acc[0] += a * p0.x; acc[1] += a * p0.y;
            acc[2] += a * p1.x; acc[3] += a * p1.y;
            acc[4] += a * p2.x; acc[5] += a * p2.y;
            acc[6] += a * p3.x; acc[7] += a * p3.y;
        }
    }
    if (ss) {
#pragma unroll
        for (int k = 0; k < 8; ++k) red[ss - 1][ds * 8 + k] = acc[k];
    }
    __syncthreads();
    if (ss == 0) {
#pragma unroll
        for (int k = 0; k < 8; ++k) {
            float v = acc[k];
#pragma unroll
            for (int sl = 0; sl < 15; ++sl) v += red[sl][ds * 8 + k];
            out[b * H2_ + d0 + ds * 8 + k] = v * inv;
        }
    }
}

// ---------------------------------------------------------------------------
extern "C" void kernel_launch(void* const* d_in, const int* in_sizes, int n_in,
                              void* d_out, int out_size) {
    const float* h      = (const float*)d_in[0];
    const int*   h_mask = (const int*)  d_in[1];
    const float* ht     = (const float*)d_in[2];
    const float* w1_w   = (const float*)d_in[3];
    const float* w1_b   = (const float*)d_in[4];
    const float* u_w    = (const float*)d_in[5];
    float* out = (float*)d_out;

    cudaFuncSetAttribute(k_gemm_beta,
                         cudaFuncAttributeMaxDynamicSharedMemorySize,
                         GEMM_SMEM);

    k_mask<<<B_, S_>>>(h_mask);
    k_prep<<<NGATH + NCVT_W + NHT, 256>>>(h, w1_w, ht);
    k_c<<<dim3(ATT_ / 8, B_ / 8), 256>>>(w1_w, w1_b);
    k_gemm_beta<<<dim3(ATT_ / BN, (B_ * S_) / BM), 128, GEMM_SMEM>>>(u_w);
    k_out<<<dim3(8, B_), 256>>>(out);
}

// round 16
// speedup vs baseline: 1.4065x; 1.0855x over previous
#include <cuda_runtime.h>
#include <cuda_fp16.h>
#include <cstdint>

// Problem constants
#define B_    64
#define S_    512
#define T_    32
#define H2_   1024
#define ATT_  512
#define WSTR_ 2048

// GEMM tiling (fp16 mma.m16n8k16, fp32 accum)
#define BM 128
#define BN 128
#define BK 32
#define NIT (H2_ / BK)          // 32
#define ROWB 80                 // padded smem row bytes (conflict-free ldmatrix)
#define A_BYTES (BM * ROWB)     // 10240
#define B_BYTES (BN * ROWB)     // 10240
#define STAGE (A_BYTES + B_BYTES)          // 20480
#define NSTAGE 3
#define GEMM_SMEM (NSTAGE * STAGE)         // 61440

// k_prep role split
#define NGATH (B_ * S_)                    // 32768 gather blocks (1 row each)
#define NCVT_W ((ATT_ * H2_) / 2048)       // 256 blocks
#define NHT    ((B_ * H2_) / 256)          // 256 blocks

// Scratch (device globals; zero-initialized — unwritten padding rows stay 0
// on every run and are never consumed downstream)
__device__ __half g_h16[(size_t)B_ * S_ * H2_];   // globally compacted fp16 h
__device__ __half g_w16[ATT_ * H2_];              // fp16 copy of w1_w[:, :1024]
__device__ float  g_ht_mean[B_ * H2_];
__device__ float  g_c[B_ * ATT_];
__device__ float  g_beta_part[4][B_ * S_];
__device__ int    g_sidx[B_ * S_];                // per-batch j -> original s
__device__ int    g_nv[B_];                       // valid count per batch
__device__ int    g_off[B_ + 1];                  // global row offsets
__device__ int    g_rowb[B_ * S_];                // global row -> batch id

// ---------------------------------------------------------------------------
__device__ __forceinline__ void cp16(uint32_t smem_dst, const void* gsrc) {
    asm volatile("cp.async.cg.shared.global [%0], [%1], 16;\n"
                 :: "r"(smem_dst), "l"(gsrc));
}
#define CP_COMMIT asm volatile("cp.async.commit_group;\n" ::: "memory")
#define CP_WAIT1  asm volatile("cp.async.wait_group 1;\n" ::: "memory")

__device__ __forceinline__ uint32_t smem_u32(const void* p) {
    uint32_t a;
    asm("{ .reg .u64 t; cvta.to.shared.u64 t, %1; cvt.u32.u64 %0, t; }"
        : "=r"(a) : "l"(p));
    return a;
}

__device__ __forceinline__ void mma_f16(float* d, const uint32_t* a,
                                        const uint32_t* b) {
    asm volatile(
        "mma.sync.aligned.m16n8k16.row.col.f32.f16.f16.f32 "
        "{%0,%1,%2,%3}, {%4,%5,%6,%7}, {%8,%9}, {%0,%1,%2,%3};\n"
        : "+f"(d[0]), "+f"(d[1]), "+f"(d[2]), "+f"(d[3])
        : "r"(a[0]), "r"(a[1]), "r"(a[2]), "r"(a[3]), "r"(b[0]), "r"(b[1]));
}

__device__ __forceinline__ void ldsm_x4(uint32_t& r0, uint32_t& r1,
                                        uint32_t& r2, uint32_t& r3,
                                        uint32_t addr) {
    asm volatile(
        "ldmatrix.sync.aligned.m8n8.x4.shared.b16 {%0,%1,%2,%3}, [%4];"
        : "=r"(r0), "=r"(r1), "=r"(r2), "=r"(r3) : "r"(addr));
}

__device__ __forceinline__ float tanh_hw(float x) {
    float t;
    asm("tanh.approx.f32 %0, %1;" : "=f"(t) : "f"(x));
    return t;
}

__device__ __forceinline__ uint4 cvt8(const float* src) {
    float4 f0 = *reinterpret_cast<const float4*>(src);
    float4 f1 = *reinterpret_cast<const float4*>(src + 4);
    __half2 a = __floats2half2_rn(f0.x, f0.y);
    __half2 b = __floats2half2_rn(f0.z, f0.w);
    __half2 c = __floats2half2_rn(f1.x, f1.y);
    __half2 d = __floats2half2_rn(f1.z, f1.w);
    uint4 v;
    v.x = *reinterpret_cast<uint32_t*>(&a);
    v.y = *reinterpret_cast<uint32_t*>(&b);
    v.z = *reinterpret_cast<uint32_t*>(&c);
    v.w = *reinterpret_cast<uint32_t*>(&d);
    return v;
}

// ---------------------------------------------------------------------------
// Mask compaction: per batch, prefix-scan h_mask -> g_sidx, g_nv.
// ---------------------------------------------------------------------------
__global__ void k_mask(const int* __restrict__ h_mask) {
    const int b = blockIdx.x;
    const int s = threadIdx.x;
    __shared__ int sc[S_];
    int v = (h_mask[b * S_ + s] != 0) ? 1 : 0;
    sc[s] = v;
    __syncthreads();
#pragma unroll
    for (int off = 1; off < S_; off <<= 1) {
        int add = (s >= off) ? sc[s - off] : 0;
        __syncthreads();
        sc[s] += add;
        __syncthreads();
    }
    if (v) g_sidx[b * S_ + sc[s] - 1] = s;
    if (s == S_ - 1) g_nv[b] = sc[S_ - 1];
}

// Global offsets: inclusive scan of nv (64 values, one block).
__global__ void k_off() {
    __shared__ int sc[B_];
    const int t = threadIdx.x;
    sc[t] = g_nv[t];
    __syncthreads();
#pragma unroll
    for (int off = 1; off < B_; off <<= 1) {
        int add = (t >= off) ? sc[t - off] : 0;
        __syncthreads();
        sc[t] += add;
        __syncthreads();
    }
    g_off[t + 1] = sc[t];
    if (t == 0) g_off[0] = 0;
}

// ---------------------------------------------------------------------------
// Fused prep: gather-convert valid h rows into GLOBALLY compacted h16,
// record g_rowb; cvt w1_w[:, :1024] -> fp16; ht_mean. Role by block.
// ---------------------------------------------------------------------------
__global__ void k_prep(const float* __restrict__ h,
                       const float* __restrict__ w1_w,
                       const float* __restrict__ ht) {
    const int blk = blockIdx.x;
    const int tid = threadIdx.x;
    if (blk < NGATH) {
        const int b = blk >> 9;
        const int j = blk & 511;
        if (j < g_nv[b]) {
            const int g = g_off[b] + j;
            const int s = g_sidx[b * S_ + j];
            float4 f = *reinterpret_cast<const float4*>(
                h + ((size_t)b * S_ + s) * H2_ + tid * 4);
            __half2 lo = __floats2half2_rn(f.x, f.y);
            __half2 hi = __floats2half2_rn(f.z, f.w);
            uint2 v;
            v.x = *reinterpret_cast<uint32_t*>(&lo);
            v.y = *reinterpret_cast<uint32_t*>(&hi);
            *reinterpret_cast<uint2*>(
                g_h16 + (size_t)g * H2_ + tid * 4) = v;
            if (tid == 0) g_rowb[g] = b;
        }
    } else if (blk < NGATH + NCVT_W) {
        size_t i = ((size_t)(blk - NGATH) * 256 + tid) * 8;
        int row = (int)(i >> 10);
        int col = (int)(i & 1023);
        *reinterpret_cast<uint4*>(&g_w16[i]) =
            cvt8(w1_w + (size_t)row * WSTR_ + col);
    } else {
        int idx = (blk - NGATH - NCVT_W) * 256 + tid;
        int b = idx >> 10;
        const float* p = ht + (size_t)b * T_ * H2_ + (idx & (H2_ - 1));
        float s = 0.f;
#pragma unroll
        for (int t = 0; t < T_; ++t) s += p[(size_t)t * H2_];
        g_ht_mean[idx] = s * (1.0f / T_);
    }
}

// ---------------------------------------------------------------------------
// c[b,a] = dot(ht_mean[b], w1_w[a,1024:]) + bias[a]
// ---------------------------------------------------------------------------
__global__ __launch_bounds__(256) void k_c(const float* __restrict__ w1_w,
                                           const float* __restrict__ w1_b) {
    __shared__ float sw[8][H2_];
    __shared__ float shm[8][H2_];
    const int a0 = blockIdx.x * 8;
    const int b0 = blockIdx.y * 8;
    const int tid = threadIdx.x;
    for (int i = tid; i < 8 * 256; i += 256) {
        int row = i >> 8, c4 = i & 255;
        reinterpret_cast<float4*>(sw[row])[c4] =
            *reinterpret_cast<const float4*>(
                w1_w + (size_t)(a0 + row) * WSTR_ + H2_ + c4 * 4);
        reinterpret_cast<float4*>(shm[row])[c4] =
            *reinterpret_cast<const float4*>(
                g_ht_mean + (b0 + row) * H2_ + c4 * 4);
    }
    __syncthreads();
    const int wid = tid >> 5, lane = tid & 31;
    const float bias = w1_b[a0 + wid];
    const float4* swv = reinterpret_cast<const float4*>(sw[wid]);

    float acc[8];
#pragma unroll
    for (int bi = 0; bi < 8; ++bi) acc[bi] = 0.f;

#pragma unroll
    for (int q = 0; q < 8; ++q) {
        float4 wv = swv[lane + q * 32];
#pragma unroll
        for (int bi = 0; bi < 8; ++bi) {
            float4 hv =
                reinterpret_cast<const float4*>(shm[bi])[lane + q * 32];
            acc[bi] += hv.x * wv.x + hv.y * wv.y + hv.z * wv.z + hv.w * wv.w;
        }
    }
#pragma unroll
    for (int bi = 0; bi < 8; ++bi) {
#pragma unroll
        for (int off = 16; off; off >>= 1)
            acc[bi] += __shfl_down_sync(0xffffffffu, acc[bi], off);
        if (lane == 0) g_c[(b0 + bi) * ATT_ + a0 + wid] = acc[bi] + bias;
    }
}

// ---------------------------------------------------------------------------
// Main fused GEMM (fp16 HMMA, fp32 accum), 128x128 CTA tile, 128 threads,
// 4 warps with 64x64 warp tiles, 3 CTAs/SM, pure cp.async, 3-stage ring.
// Globally compacted row space; tiles past total exit immediately.
// Prefetch issued AFTER the MMA block (R11 post-mortem: hoisting cp.async
// between barrier and LDSM costs ~10us; keep it here).
// ---------------------------------------------------------------------------
__global__ __launch_bounds__(128, 3) void k_gemm_beta(
    const float* __restrict__ u_w)
{
    extern __shared__ char smem[];
    const uint32_t sb = smem_u32(smem);

    const int tid = threadIdx.x;
    const int lane = tid & 31;
    const int wid = tid >> 5;
    const int warp_m = wid >> 1;
    const int warp_n = wid & 1;
    const int r = lane >> 2;
    const int t = lane & 3;

    const int n0 = blockIdx.x * BN;
    const int m0 = blockIdx.y * BM;

    // global-compaction early exit
    if (m0 >= g_off[B_]) return;

    const int lane7 = lane & 7;
    const int lg8 = (lane >> 3) & 1;
    const int lg16 = lane >> 4;
    const uint32_t a_off =
        (uint32_t)((warp_m * 64 + lg8 * 8 + lane7) * ROWB + lg16 * 16);
    const uint32_t b_off =
        (uint32_t)(A_BYTES + (warp_n * 64 + lg8 * 8 + lane7) * ROWB +
                   lg16 * 16);

    const int crow = tid >> 2;
    const int cq = tid & 3;

    float acc[4][8][4];
#pragma unroll
    for (int i = 0; i < 4; ++i)
#pragma unroll
        for (int j = 0; j < 8; ++j)
#pragma unroll
            for (int k = 0; k < 4; ++k) acc[i][j][k] = 0.f;

    auto load_stage = [&](int it) {
        const uint32_t base = sb + (uint32_t)((it % 3) * STAGE);
        const int kb = it * BK;
#pragma unroll
        for (int s = 0; s < 4; ++s) {
            int row = crow + s * 32;
            cp16(base + (uint32_t)(row * ROWB + cq * 16),
                 g_h16 + (size_t)(m0 + row) * H2_ + kb + cq * 8);
        }
#pragma unroll
        for (int s = 0; s < 4; ++s) {
            int row = crow + s * 32;
            cp16(base + A_BYTES + (uint32_t)(row * ROWB + cq * 16),
                 g_w16 + (size_t)(n0 + row) * H2_ + kb + cq * 8);
        }
        CP_COMMIT;
    };

    load_stage(0);
    load_stage(1);

    for (int it = 0; it < NIT; ++it) {
        CP_WAIT1;
        __syncthreads();

        const uint32_t sbase = sb + (uint32_t)((it % 3) * STAGE);
        const uint32_t abase = sbase + a_off;
        const uint32_t bbase = sbase + b_off;

#pragma unroll
        for (int ks = 0; ks < 2; ++ks) {
            uint32_t af[4][4], bf[8][2];
#pragma unroll
            for (int mf = 0; mf < 4; ++mf)
                ldsm_x4(af[mf][0], af[mf][1], af[mf][2], af[mf][3],
                        abase + mf * 1280 + ks * 32);
#pragma unroll
            for (int nfp = 0; nfp < 4; ++nfp)
                ldsm_x4(bf[2 * nfp][0], bf[2 * nfp + 1][0],
                        bf[2 * nfp][1], bf[2 * nfp + 1][1],
                        bbase + nfp * 1280 + ks * 32);
#pragma unroll
            for (int mf = 0; mf < 4; ++mf)
#pragma unroll
                for (int nf = 0; nf < 8; ++nf)
                    mma_f16(acc[mf][nf], af[mf], bf[nf]);
        }

        if (it + 2 < NIT) load_stage(it + 2);
        else CP_COMMIT;
    }

    // ---- fused epilogue (per-row batch lookup for c) ----
    float uv[8][2];
    int ncol[8][2];
#pragma unroll
    for (int nf = 0; nf < 8; ++nf)
#pragma unroll
        for (int j = 0; j < 2; ++j) {
            int n = n0 + warp_n * 64 + nf * 8 + t * 2 + j;
            uv[nf][j] = u_w[n];
            ncol[nf][j] = n;
        }

    float part[4][2];
#pragma unroll
    for (int mf = 0; mf < 4; ++mf)
#pragma unroll
        for (int half = 0; half < 2; ++half) {
            int row = m0 + warp_m * 64 + mf * 16 + half * 8 + r;
            const float* cb = g_c + g_rowb[row] * ATT_;
            float p = 0.f;
#pragma unroll
            for (int nf = 0; nf < 8; ++nf)
#pragma unroll
                for (int j = 0; j < 2; ++j) {
                    float z = acc[mf][nf][half * 2 + j] + cb[ncol[nf][j]];
                    p += uv[nf][j] * tanh_hw(z);
                }
            part[mf][half] = p;
        }

#pragma unroll
    for (int mf = 0; mf < 4; ++mf)
#pragma unroll
        for (int half = 0; half < 2; ++half) {
            float p = part[mf][half];
            p += __shfl_xor_sync(0xffffffffu, p, 1);
            p += __shfl_xor_sync(0xffffffffu, p, 2);
            part[mf][half] = p;
        }

    __syncthreads();
    float* red = reinterpret_cast<float*>(smem);   // [128][2]
    if (t == 0) {
#pragma unroll
        for (int mf = 0; mf < 4; ++mf)
#pragma unroll
            for (int half = 0; half < 2; ++half) {
                int row = warp_m * 64 + mf * 16 + half * 8 + r;
                red[row * 2 + warp_n] = part[mf][half];
            }
    }
    __syncthreads();
    if (tid < BM)
        g_beta_part[blockIdx.x][m0 + tid] = red[tid * 2] + red[tid * 2 + 1];
}

// ---------------------------------------------------------------------------
// Fused softmax + weighted sum over batch segment [off, off+nv).
// grid (8 d-chunks of 128, 64 b), 256 threads.
// ---------------------------------------------------------------------------
__global__ __launch_bounds__(256) void k_out(float* __restrict__ out) {
    const int b = blockIdx.y;
    const int d0 = blockIdx.x * 128;
    const int tid = threadIdx.x;
    const int ds = tid & 15;
    const int ss = tid >> 4;
    const int off = g_off[b];
    const int nv = g_off[b + 1] - off;

    __shared__ float salpha[S_];
    __shared__ float tmp[256];
    __shared__ float red[15][128];

    float beta[2];
#pragma unroll
    for (int k = 0; k < 2; ++k) {
        int j = tid + k * 256;
        int idx = off + j;
        float v = g_beta_part[0][idx] + g_beta_part[1][idx] +
                  g_beta_part[2][idx] + g_beta_part[3][idx];
        beta[k] = (j < nv) ? v : -1e20f;
    }
    tmp[tid] = fmaxf(beta[0], beta[1]);
    __syncthreads();
#pragma unroll
    for (int o = 128; o; o >>= 1) {
        if (tid < o) tmp[tid] = fmaxf(tmp[tid], tmp[tid + o]);
        __syncthreads();
    }
    const float mx = tmp[0];
    __syncthreads();
    float e0 = __expf(beta[0] - mx);
    float e1 = __expf(beta[1] - mx);
    salpha[tid] = e0;
    salpha[tid + 256] = e1;
    tmp[tid] = e0 + e1;
    __syncthreads();
#pragma unroll
    for (int o = 128; o; o >>= 1) {
        if (tid < o) tmp[tid] += tmp[tid + o];
        __syncthreads();
    }
    const float inv = 1.0f / tmp[0];
    __syncthreads();

    float acc[8];
#pragma unroll
    for (int k = 0; k < 8; ++k) acc[k] = 0.f;
    if (ss * 32 < nv) {
        const __half* hp =
            g_h16 + ((size_t)off + ss * 32) * H2_ + d0 + ds * 8;
        const float* al = salpha + ss * 32;
        const int smax = min(32, nv - ss * 32);
        for (int s = 0; s < smax; ++s) {
            uint4 v = *reinterpret_cast<const uint4*>(hp + (size_t)s * H2_);
            float a = al[s];
            float2 p0 = __half22float2(*reinterpret_cast<__half2*>(&v.x));
            float2 p1 = __half22float2(*reinterpret_cast<__half2*>(&v.y));
            float2 p2 = __half22float2(*reinterpret_cast<__half2*>(&v.z));
            float2 p3 = __half22float2(*reinterpret_cast<__half2*>(&v.w));
            acc[0] += a * p0.x; acc[1] += a * p0.y;
            acc[2] += a * p1.x; acc[3] += a * p1.y;
            acc[4] += a * p2.x; acc[5] += a * p2.y;
            acc[6] += a * p3.x; acc[7] += a * p3.y;
        }
    }
    if (ss) {
#pragma unroll
        for (int k = 0; k < 8; ++k) red[ss - 1][ds * 8 + k] = acc[k];
    }
    __syncthreads();
    if (ss == 0) {
#pragma unroll
        for (int k = 0; k < 8; ++k) {
            float v = acc[k];
#pragma unroll
            for (int sl = 0; sl < 15; ++sl) v += red[sl][ds * 8 + k];
            out[b * H2_ + d0 + ds * 8 + k] = v * inv;
        }
    }
}

// ---------------------------------------------------------------------------
extern "C" void kernel_launch(void* const* d_in, const int* in_sizes, int n_in,
                              void* d_out, int out_size) {
    const float* h      = (const float*)d_in[0];
    const int*   h_mask = (const int*)  d_in[1];
    const float* ht     = (const float*)d_in[2];
    const float* w1_w   = (const float*)d_in[3];
    const float* w1_b   = (const float*)d_in[4];
    const float* u_w    = (const float*)d_in[5];
    float* out = (float*)d_out;

    cudaFuncSetAttribute(k_gemm_beta,
                         cudaFuncAttributeMaxDynamicSharedMemorySize,
                         GEMM_SMEM);

    k_mask<<<B_, S_>>>(h_mask);
    k_off<<<1, B_>>>();
    k_prep<<<NGATH + NCVT_W + NHT, 256>>>(h, w1_w, ht);
    k_c<<<dim3(ATT_ / 8, B_ / 8), 256>>>(w1_w, w1_b);
    k_gemm_beta<<<dim3(ATT_ / BN, (B_ * S_) / BM), 128, GEMM_SMEM>>>(u_w);
    k_out<<<dim3(8, B_), 256>>>(out);
}